// round 6
// baseline (speedup 1.0000x reference)
#include <cuda_runtime.h>
#include <cuda_bf16.h>
#include <cstdint>

#define MAXN 50000
#define MAXE 800000
#define LLAYERS 3

// ================= helpers =================
__device__ __forceinline__ uint32_t packbf(float lo_v, float hi_v) {
    uint32_t r;
    asm("cvt.rn.satfinite.bf16x2.f32 %0, %1, %2;" : "=r"(r) : "f"(hi_v), "f"(lo_v));
    return r;
}
__device__ __forceinline__ float bfl(uint32_t p) { return __uint_as_float(p << 16); }
__device__ __forceinline__ float bfh(uint32_t p) { return __uint_as_float(p & 0xffff0000u); }

__device__ __forceinline__ void pack_hl(float v0, float v1, uint32_t& h, uint32_t& l) {
    h = packbf(v0, v1);
    l = packbf(v0 - bfl(h), v1 - bfh(h));
}

__device__ __forceinline__ void mma_bf16(float* c, const uint32_t* a, uint32_t b0, uint32_t b1) {
    asm volatile(
        "mma.sync.aligned.m16n8k16.row.col.f32.bf16.bf16.f32 "
        "{%0,%1,%2,%3}, {%4,%5,%6,%7}, {%8,%9}, {%0,%1,%2,%3};\n"
        : "+f"(c[0]), "+f"(c[1]), "+f"(c[2]), "+f"(c[3])
        : "r"(a[0]), "r"(a[1]), "r"(a[2]), "r"(a[3]), "r"(b0), "r"(b1));
}

// fragment-pair interleaved offset within a K-row: for element k,
// chunk j = k>>4; within chunk, groups of 4 elems {2g,2g+1,2g+8,2g+9}
// so that a lane's (b0,b1) 8-byte pair is contiguous (LDS.64).
__host__ __device__ __forceinline__ int wofs(int k) {
    int j = k >> 4, r = k & 15;
    return j * 16 + ((r & 7) >> 1) * 4 + ((r >> 3) << 1) + (r & 1);
}

// ================= scratch (static device globals) =================
__device__ float g_h1n[MAXN * 256];
__device__ float g_ab [MAXN * 256];
__device__ float g_x  [MAXN * 128];
__device__ float g_agg[MAXN * 128];
__device__ float g_deg[MAXN];
__device__ float g_Wab [LLAYERS * 256 * 256];
__device__ float g_Wc  [LLAYERS * 128 * 128];
__device__ float g_bch [LLAYERS * 256];   // [bc/2 | bc/2]
// per-layer packed bf16 transposed edge weights, 88064 elems / layer
#define WP_LAYER_ELEMS 88064
__device__ uint4 g_wpack[LLAYERS * WP_LAYER_ELEMS * 2 / 16];
// per-layer node weights: [W1hi 256x136][W1lo][WABhi 256x264][WABlo]
#define NP_LAYER_ELEMS 204800
#define NP_W1  0
#define NP_WAB 69632
__device__ uint4 g_wnode[LLAYERS * NP_LAYER_ELEMS * 2 / 16];
__device__ uint4 g_wf[2 * 64 * 136 * 2 / 16];

#define WO_WE1H 0
#define WO_WE1L 9216
#define WO_WCH  18432
#define WO_WCL  35840
#define WO_WM2H 53248
#define WO_WM2L 70656

// ================= fused weight-fuse kernel =================
// blocks [0,768): Wab ; [768,960): Wc ; [960,1008): bch
__global__ __launch_bounds__(256) void fuse_all(
    const float* __restrict__ Wn2, const float* __restrict__ Wm1,
    const float* __restrict__ We2, const float* __restrict__ bn2,
    const float* __restrict__ be2, const float* __restrict__ bm1,
    float* __restrict__ Wab, float* __restrict__ Wc, float* __restrict__ bch)
{
    int b = blockIdx.x, tid = threadIdx.x;
    if (b < 768) {
        int l = b >> 8;
        int idx = (b & 255) * 256 + tid;
        const float* wn2 = Wn2 + (size_t)l * 256 * 128;
        const float* wm1 = Wm1 + (size_t)l * 320 * 128;
        int k = idx >> 8, j = idx & 255;
        const float* wm = (j < 128) ? (wm1 + j) : (wm1 + 128 * 128 + (j - 128));
        float acc = 0.f;
        #pragma unroll 4
        for (int t = 0; t < 128; t++) acc += wn2[k * 128 + t] * wm[t * 128];
        Wab[(size_t)l * 65536 + idx] = acc;
    } else if (b < 960) {
        int lb = b - 768;
        int l = lb / 64;
        int idx = (lb % 64) * 256 + tid;
        const float* we2 = We2 + (size_t)l * 128 * 64;
        const float* wm1 = Wm1 + (size_t)l * 320 * 128;
        int k = idx >> 7, j = idx & 127;
        float acc = 0.f;
        #pragma unroll 4
        for (int t = 0; t < 64; t++) acc += we2[k * 64 + t] * wm1[(256 + t) * 128 + j];
        Wc[(size_t)l * 16384 + idx] = acc;
    } else {
        int lb = b - 960;
        int l = lb / 16;
        int lane = tid & 31;
        int j = (lb % 16) * 8 + (tid >> 5);
        const float* wm1 = Wm1 + (size_t)l * 320 * 128;
        const float* bn2l = bn2 + l * 128;
        const float* be2l = be2 + l * 64;
        float acc = 0.f;
        #pragma unroll
        for (int k = lane; k < 128; k += 32)
            acc += bn2l[k] * (wm1[k * 128 + j] + wm1[(128 + k) * 128 + j]);
        #pragma unroll
        for (int t = lane; t < 64; t += 32)
            acc += be2l[t] * wm1[(256 + t) * 128 + j];
        #pragma unroll
        for (int o = 16; o; o >>= 1) acc += __shfl_xor_sync(0xffffffffu, acc, o);
        if (lane == 0) {
            float half = 0.5f * (bm1[l * 128 + j] + acc);
            bch[l * 256 + j] = half;
            bch[l * 256 + 128 + j] = half;
        }
    }
}

// ================= fused bf16 hi/lo transpose prep kernel =================
__device__ __forceinline__ void splitw(float w, __nv_bfloat16* hi, __nv_bfloat16* lo, int o) {
    __nv_bfloat16 h = __float2bfloat16(w);
    hi[o] = h;
    lo[o] = __float2bfloat16(w - __bfloat162float(h));
}

// blocks: [0,96) we1t | [96,288) WcT | [288,480) Wm2T | [480,864) W1 | [864,1632) WAB | [1632,1664) Wf
__global__ __launch_bounds__(256) void prep_all(
    const float* __restrict__ We1, const float* __restrict__ WcG,
    const float* __restrict__ Wm2, const float* __restrict__ Wn1,
    const float* __restrict__ WabG, const float* __restrict__ Wf,
    __nv_bfloat16* __restrict__ wb, __nv_bfloat16* __restrict__ nbw,
    __nv_bfloat16* __restrict__ wfb)
{
    int b = blockIdx.x, tid = threadIdx.x;
    if (b < 96) {
        int l = b / 32;
        int idx = (b % 32) * 256 + tid;             // 8192 ; K=64, KP=72
        int n = idx >> 6, k = idx & 63;
        float w = We1[(size_t)l * 8192 + k * 128 + n];
        __nv_bfloat16* base = wb + (size_t)l * WP_LAYER_ELEMS;
        splitw(w, base + WO_WE1H, base + WO_WE1L, n * 72 + wofs(k));
    } else if (b < 288) {
        int lb = b - 96;
        int l = lb / 64;
        int idx = (lb % 64) * 256 + tid;            // 16384 ; K=128, KP=136
        int n = idx >> 7, k = idx & 127;
        float w = WcG[(size_t)l * 16384 + k * 128 + n];
        __nv_bfloat16* base = wb + (size_t)l * WP_LAYER_ELEMS;
        splitw(w, base + WO_WCH, base + WO_WCL, n * 136 + wofs(k));
    } else if (b < 480) {
        int lb = b - 288;
        int l = lb / 64;
        int idx = (lb % 64) * 256 + tid;            // 16384 ; K=128, KP=136
        int n = idx >> 7, k = idx & 127;
        float w = Wm2[(size_t)l * 16384 + k * 128 + n];
        __nv_bfloat16* base = wb + (size_t)l * WP_LAYER_ELEMS;
        splitw(w, base + WO_WM2H, base + WO_WM2L, n * 136 + wofs(k));
    } else if (b < 864) {
        int lb = b - 480;
        int l = lb / 128;
        int idx = (lb % 128) * 256 + tid;           // 32768 ; K=128,Nf=256,KP=136
        int n = idx & 255, k = idx >> 8;
        float w = Wn1[(size_t)l * 32768 + idx];
        __nv_bfloat16* base = nbw + (size_t)l * NP_LAYER_ELEMS + NP_W1;
        splitw(w, base, base + 256 * 136, n * 136 + wofs(k));
    } else if (b < 1632) {
        int lb = b - 864;
        int l = lb / 256;
        int idx = (lb % 256) * 256 + tid;           // 65536 ; K=256,Nf=256,KP=264
        int n = idx & 255, k = idx >> 8;
        float w = WabG[(size_t)l * 65536 + idx];
        __nv_bfloat16* base = nbw + (size_t)l * NP_LAYER_ELEMS + NP_WAB;
        splitw(w, base, base + 256 * 264, n * 264 + wofs(k));
    } else {
        int idx = (b - 1632) * 256 + tid;           // 8192 ; K=128,Nf=64,KP=136
        int n = idx & 63, k = idx >> 6;
        splitw(Wf[idx], wfb, wfb + 64 * 136, n * 136 + wofs(k));
    }
}

// ================= init (zero agg + deg) + degree =================
__global__ void zero_init(float* __restrict__ agg, float* __restrict__ deg, int N) {
    int i = blockIdx.x * blockDim.x + threadIdx.x;
    if (i < N * 32) ((float4*)agg)[i] = make_float4(0.f, 0.f, 0.f, 0.f);
    if (i < N) deg[i] = 0.f;
}

__global__ void deg_kernel(const int* __restrict__ dst, float* __restrict__ deg, int E) {
    int e = blockIdx.x * blockDim.x + threadIdx.x;
    if (e < E) atomicAdd(&deg[dst[e]], 1.f);
}

// ================= tensor-core node GEMM =================
template<int KCH, int NB, bool RELU>
__global__ __launch_bounds__(256) void ngemm(
    const float* __restrict__ A, const uint4* __restrict__ Wt,
    const float* __restrict__ bias, float* __restrict__ C, int M, int Nfull)
{
    constexpr int K = KCH * 16;
    constexpr int KP = K + 8;
    constexpr int NT = NB * 8;
    extern __shared__ char nsm[];
    __nv_bfloat16* Whs = (__nv_bfloat16*)nsm;
    __nv_bfloat16* Wls = Whs + NT * KP;
    float* bs = (float*)(Wls + NT * KP);

    int tid = threadIdx.x;
    int n0 = blockIdx.y * NT;
    {
        const uint4* hsrc = Wt + n0 * KP / 8;
        const uint4* lsrc = Wt + (Nfull * KP) / 8 + n0 * KP / 8;
        uint4* hdst = (uint4*)Whs;
        uint4* ldst = (uint4*)Wls;
        constexpr int CNT = NT * KP / 8;
        for (int i = tid; i < CNT; i += 256) { hdst[i] = hsrc[i]; ldst[i] = lsrc[i]; }
        if (tid < NT) bs[tid] = bias ? bias[n0 + tid] : 0.f;
    }
    __syncthreads();

    int lane = tid & 31, wid = tid >> 5;
    int qr = lane >> 2, qc = (lane & 3) * 2;
    int m0 = (blockIdx.x * 8 + wid) * 16;
    int r0 = m0 + qr, r1 = r0 + 8;
    bool v0 = r0 < M, v1 = r1 < M;
    const float* a0 = A + (size_t)(v0 ? r0 : 0) * K;
    const float* a1 = A + (size_t)(v1 ? r1 : 0) * K;

    float acc[NB][4];
    #pragma unroll
    for (int nb = 0; nb < NB; nb++) {
        acc[nb][0] = acc[nb][1] = acc[nb][2] = acc[nb][3] = 0.f;
    }

    #pragma unroll 2
    for (int j = 0; j < KCH; j++) {
        uint32_t Ah[4], Al[4];
        float2 x0 = *(const float2*)(a0 + 16 * j + qc);
        float2 x1 = *(const float2*)(a1 + 16 * j + qc);
        float2 x2 = *(const float2*)(a0 + 16 * j + qc + 8);
        float2 x3 = *(const float2*)(a1 + 16 * j + qc + 8);
        pack_hl(x0.x, x0.y, Ah[0], Al[0]);
        pack_hl(x1.x, x1.y, Ah[1], Al[1]);
        pack_hl(x2.x, x2.y, Ah[2], Al[2]);
        pack_hl(x3.x, x3.y, Ah[3], Al[3]);
        int fo = j * 16 + (qc >> 1) * 4;
        #pragma unroll
        for (int nb = 0; nb < NB; nb++) {
            const __nv_bfloat16* ph = Whs + (8 * nb + qr) * KP + fo;
            const __nv_bfloat16* pl = Wls + (8 * nb + qr) * KP + fo;
            uint2 bh = *(const uint2*)ph;
            uint2 bl = *(const uint2*)pl;
            mma_bf16(acc[nb], Ah, bh.x, bh.y);
            mma_bf16(acc[nb], Ah, bl.x, bl.y);
            mma_bf16(acc[nb], Al, bh.x, bh.y);
        }
    }

    #pragma unroll
    for (int nb = 0; nb < NB; nb++) {
        int col = 8 * nb + qc;
        float b0v = bs[col], b1v = bs[col + 1];
        float u0 = acc[nb][0] + b0v, u1 = acc[nb][1] + b1v;
        float u2 = acc[nb][2] + b0v, u3 = acc[nb][3] + b1v;
        if (RELU) {
            u0 = fmaxf(u0, 0.f); u1 = fmaxf(u1, 0.f);
            u2 = fmaxf(u2, 0.f); u3 = fmaxf(u3, 0.f);
        }
        if (v0) *(float2*)(C + (size_t)r0 * Nfull + n0 + col) = make_float2(u0, u1);
        if (v1) *(float2*)(C + (size_t)r1 * Nfull + n0 + col) = make_float2(u2, u3);
    }
}

// ================= mma.sync fused edge kernel (384 threads) =================
#define EDGE3_SMEM (176128 + 1024)
#define EDGE_THREADS 384
#define EDGE_WARPS 12

template<int NC>
__device__ __forceinline__ void stage_mma(
    float acc[16][4], const uint32_t Ah[8][4], const uint32_t Al[8][4],
    const __nv_bfloat16* __restrict__ Wh, const __nv_bfloat16* __restrict__ Wl,
    int KP, int qr, int qc)
{
    #pragma unroll
    for (int j = 0; j < NC; j++) {
        int fo = j * 16 + (qc >> 1) * 4;
        #pragma unroll
        for (int nb = 0; nb < 16; nb++) {
            const __nv_bfloat16* ph = Wh + (8 * nb + qr) * KP + fo;
            const __nv_bfloat16* pl = Wl + (8 * nb + qr) * KP + fo;
            uint2 bh = *(const uint2*)ph;
            uint2 bl = *(const uint2*)pl;
            mma_bf16(acc[nb], Ah[j], bh.x, bh.y);
            mma_bf16(acc[nb], Ah[j], bl.x, bl.y);
            mma_bf16(acc[nb], Al[j], bh.x, bh.y);
        }
    }
}

__global__ __launch_bounds__(EDGE_THREADS, 1) void edge_kernel3(
    const float* __restrict__ ea,
    const int* __restrict__ src, const int* __restrict__ dst,
    const uint4* __restrict__ wpack,
    const float* __restrict__ be1,
    const float* __restrict__ ab, float* __restrict__ agg, int E)
{
    extern __shared__ char smem[];
    __nv_bfloat16* W = (__nv_bfloat16*)smem;
    float* be1s = (float*)(smem + 176128);

    int tid = threadIdx.x;
    {
        uint4* s4 = (uint4*)smem;
        for (int i = tid; i < 11008; i += EDGE_THREADS) s4[i] = wpack[i];
        if (tid < 128) be1s[tid] = be1[tid];
    }
    __syncthreads();

    const __nv_bfloat16* We1h = W + WO_WE1H;
    const __nv_bfloat16* We1l = W + WO_WE1L;
    const __nv_bfloat16* Wch  = W + WO_WCH;
    const __nv_bfloat16* Wcl  = W + WO_WCL;
    const __nv_bfloat16* Wm2h = W + WO_WM2H;
    const __nv_bfloat16* Wm2l = W + WO_WM2L;

    int lane = tid & 31, wid = tid >> 5;
    int qr = lane >> 2;
    int qc = (lane & 3) * 2;

    int nG = (E + 15) >> 4;
    for (int g = blockIdx.x * EDGE_WARPS + wid; g < nG; g += gridDim.x * EDGE_WARPS) {
        int e0 = g << 4;
        int er0 = e0 + qr, er1 = er0 + 8;
        bool v0 = er0 < E, v1 = er1 < E;
        int ec0 = v0 ? er0 : 0, ec1 = v1 ? er1 : 0;
        int d0 = dst[ec0], d1 = dst[ec1];
        int s0 = src[ec0], s1 = src[ec1];

        uint32_t Ah[8][4], Al[8][4];
        float acc[16][4];

        #pragma unroll
        for (int j = 0; j < 4; j++) {
            const float* r0p = ea + (size_t)ec0 * 64 + 16 * j + qc;
            const float* r1p = ea + (size_t)ec1 * 64 + 16 * j + qc;
            float2 x0 = *(const float2*)r0p;
            float2 x1 = *(const float2*)r1p;
            float2 x2 = *(const float2*)(r0p + 8);
            float2 x3 = *(const float2*)(r1p + 8);
            pack_hl(x0.x, x0.y, Ah[j][0], Al[j][0]);
            pack_hl(x1.x, x1.y, Ah[j][1], Al[j][1]);
            pack_hl(x2.x, x2.y, Ah[j][2], Al[j][2]);
            pack_hl(x3.x, x3.y, Ah[j][3], Al[j][3]);
        }

        // S1
        #pragma unroll
        for (int nb = 0; nb < 16; nb++)
            #pragma unroll
            for (int q = 0; q < 4; q++) acc[nb][q] = 0.f;
        stage_mma<4>(acc, Ah, Al, We1h, We1l, 72, qr, qc);
        #pragma unroll
        for (int nb = 0; nb < 16; nb++) {
            int col = 8 * nb + qc;
            float b0 = be1s[col], b1 = be1s[col + 1];
            float u0 = fmaxf(acc[nb][0] + b0, 0.f);
            float u1 = fmaxf(acc[nb][1] + b1, 0.f);
            float u2 = fmaxf(acc[nb][2] + b0, 0.f);
            float u3 = fmaxf(acc[nb][3] + b1, 0.f);
            int j = nb >> 1, q = (nb & 1) * 2;
            pack_hl(u0, u1, Ah[j][q],     Al[j][q]);
            pack_hl(u2, u3, Ah[j][q + 1], Al[j][q + 1]);
        }

        // S2  (bc folded into ab via bch bias in the WAB gemm)
        #pragma unroll
        for (int nb = 0; nb < 16; nb++)
            #pragma unroll
            for (int q = 0; q < 4; q++) acc[nb][q] = 0.f;
        stage_mma<8>(acc, Ah, Al, Wch, Wcl, 136, qr, qc);
        {
            const float* a0p = ab + (size_t)d0 * 256;
            const float* a1p = ab + (size_t)d1 * 256;
            const float* b0p = ab + (size_t)s0 * 256 + 128;
            const float* b1p = ab + (size_t)s1 * 256 + 128;
            #pragma unroll
            for (int nb = 0; nb < 16; nb++) {
                int col = 8 * nb + qc;
                float2 ga0 = __ldg((const float2*)(a0p + col));
                float2 ga1 = __ldg((const float2*)(a1p + col));
                float2 gb0 = __ldg((const float2*)(b0p + col));
                float2 gb1 = __ldg((const float2*)(b1p + col));
                float u0 = fmaxf(acc[nb][0] + ga0.x + gb0.x, 0.f);
                float u1 = fmaxf(acc[nb][1] + ga0.y + gb0.y, 0.f);
                float u2 = fmaxf(acc[nb][2] + ga1.x + gb1.x, 0.f);
                float u3 = fmaxf(acc[nb][3] + ga1.y + gb1.y, 0.f);
                int j = nb >> 1, q = (nb & 1) * 2;
                pack_hl(u0, u1, Ah[j][q],     Al[j][q]);
                pack_hl(u2, u3, Ah[j][q + 1], Al[j][q + 1]);
            }
        }

        // S3
        #pragma unroll
        for (int nb = 0; nb < 16; nb++)
            #pragma unroll
            for (int q = 0; q < 4; q++) acc[nb][q] = 0.f;
        stage_mma<8>(acc, Ah, Al, Wm2h, Wm2l, 136, qr, qc);
        {
            float* g0 = agg + (size_t)d0 * 128;
            float* g1 = agg + (size_t)d1 * 128;
            #pragma unroll
            for (int nb = 0; nb < 16; nb++) {
                int col = 8 * nb + qc;
                if (v0)
                    asm volatile("red.global.add.v2.f32 [%0], {%1, %2};"
                                 :: "l"(g0 + col), "f"(acc[nb][0]), "f"(acc[nb][1]) : "memory");
                if (v1)
                    asm volatile("red.global.add.v2.f32 [%0], {%1, %2};"
                                 :: "l"(g1 + col), "f"(acc[nb][2]), "f"(acc[nb][3]) : "memory");
            }
        }
    }
}

// ================= LayerNorm + relu (+ agg re-zero for next layer) =================
__global__ void ln_kernel(float* __restrict__ agg, const float* __restrict__ deg,
                          const float* __restrict__ bm2, const float* __restrict__ lnw,
                          const float* __restrict__ lnb, float* __restrict__ xout, int N)
{
    int gwarp = (blockIdx.x * blockDim.x + threadIdx.x) >> 5;
    int lane = threadIdx.x & 31;
    if (gwarp >= N) return;
    float d = deg[gwarp];
    float inv = 1.f / fmaxf(d, 1.f);
    float add = (d > 0.f) ? 1.f : 0.f;
    float4 v = ((const float4*)agg)[(size_t)gwarp * 32 + lane];
    ((float4*)agg)[(size_t)gwarp * 32 + lane] = make_float4(0.f, 0.f, 0.f, 0.f);
    float4 b = ((const float4*)bm2)[lane];
    v.x = v.x * inv + add * b.x;
    v.y = v.y * inv + add * b.y;
    v.z = v.z * inv + add * b.z;
    v.w = v.w * inv + add * b.w;
    float s = v.x + v.y + v.z + v.w;
    #pragma unroll
    for (int o = 16; o; o >>= 1) s += __shfl_xor_sync(0xffffffffu, s, o);
    float mu = s * (1.f / 128.f);
    float d0 = v.x - mu, d1 = v.y - mu, d2 = v.z - mu, d3 = v.w - mu;
    float q = d0 * d0 + d1 * d1 + d2 * d2 + d3 * d3;
    #pragma unroll
    for (int o = 16; o; o >>= 1) q += __shfl_xor_sync(0xffffffffu, q, o);
    float rs = rsqrtf(q * (1.f / 128.f) + 1e-5f);
    float4 w = ((const float4*)lnw)[lane];
    float4 bb = ((const float4*)lnb)[lane];
    float4 o;
    o.x = fmaxf(d0 * rs * w.x + bb.x, 0.f);
    o.y = fmaxf(d1 * rs * w.y + bb.y, 0.f);
    o.z = fmaxf(d2 * rs * w.z + bb.z, 0.f);
    o.w = fmaxf(d3 * rs * w.w + bb.w, 0.f);
    ((float4*)xout)[(size_t)gwarp * 32 + lane] = o;
}

// ================= host =================
extern "C" void kernel_launch(void* const* d_in, const int* in_sizes, int n_in,
                              void* d_out, int out_size)
{
    const float* x    = (const float*)d_in[0];
    const float* ea   = (const float*)d_in[1];
    const int*   eidx = (const int*)  d_in[2];
    const float* Wn1  = (const float*)d_in[3];
    const float* bn1  = (const float*)d_in[4];
    const float* Wn2  = (const float*)d_in[5];
    const float* bn2  = (const float*)d_in[6];
    const float* We1  = (const float*)d_in[7];
    const float* be1  = (const float*)d_in[8];
    const float* We2  = (const float*)d_in[9];
    const float* be2  = (const float*)d_in[10];
    const float* Wm1  = (const float*)d_in[11];
    const float* bm1  = (const float*)d_in[12];
    const float* Wm2  = (const float*)d_in[13];
    const float* bm2  = (const float*)d_in[14];
    const float* lnw  = (const float*)d_in[15];
    const float* lnb  = (const float*)d_in[16];
    const float* Wf   = (const float*)d_in[17];
    const float* bf   = (const float*)d_in[18];

    int N = in_sizes[0] / 128;
    int E = in_sizes[1] / 64;
    const int* srcp = eidx;
    const int* dstp = eidx + E;

    float *h1n, *ab, *xb, *agg, *deg, *Wab, *Wc, *bch;
    uint4 *wpack, *wnode, *wf;
    cudaGetSymbolAddress((void**)&h1n, g_h1n);
    cudaGetSymbolAddress((void**)&ab,  g_ab);
    cudaGetSymbolAddress((void**)&xb,  g_x);
    cudaGetSymbolAddress((void**)&agg, g_agg);
    cudaGetSymbolAddress((void**)&deg, g_deg);
    cudaGetSymbolAddress((void**)&Wab, g_Wab);
    cudaGetSymbolAddress((void**)&Wc,  g_Wc);
    cudaGetSymbolAddress((void**)&bch, g_bch);
    cudaGetSymbolAddress((void**)&wpack, g_wpack);
    cudaGetSymbolAddress((void**)&wnode, g_wnode);
    cudaGetSymbolAddress((void**)&wf, g_wf);
    __nv_bfloat16* wb = (__nv_bfloat16*)wpack;
    __nv_bfloat16* nbw = (__nv_bfloat16*)wnode;
    __nv_bfloat16* wfb = (__nv_bfloat16*)wf;

    cudaFuncSetAttribute(edge_kernel3, cudaFuncAttributeMaxDynamicSharedMemorySize,
                         EDGE3_SMEM);
    int smW1  = 2 * 128 * 136 * 2 + 512;   // ngemm<8,16>
    int smWab = 2 * 128 * 264 * 2 + 512;   // ngemm<16,16>
    int smWf  = 2 * 64 * 136 * 2 + 256;    // ngemm<8,8>
    cudaFuncSetAttribute(ngemm<8, 16, true>,   cudaFuncAttributeMaxDynamicSharedMemorySize, smW1);
    cudaFuncSetAttribute(ngemm<16, 16, false>, cudaFuncAttributeMaxDynamicSharedMemorySize, smWab);
    cudaFuncSetAttribute(ngemm<8, 8, false>,   cudaFuncAttributeMaxDynamicSharedMemorySize, smWf);

    zero_init<<<(N * 32 + 255) / 256, 256>>>(agg, deg, N);
    deg_kernel<<<(E + 255) / 256, 256>>>(dstp, deg, E);
    fuse_all<<<1008, 256>>>(Wn2, Wm1, We2, bn2, be2, bm1, Wab, Wc, bch);
    prep_all<<<1664, 256>>>(We1, Wc, Wm2, Wn1, Wab, Wf, wb, nbw, wfb);

    const float* curx = x;
    int gRows = (N + 127) / 128;
    for (int l = 0; l < LLAYERS; l++) {
        __nv_bfloat16* npb = nbw + (size_t)l * NP_LAYER_ELEMS;
        ngemm<8, 16, true><<<dim3(gRows, 2), 256, smW1>>>(
            curx, (const uint4*)(npb + NP_W1), bn1 + l * 256, h1n, N, 256);
        ngemm<16, 16, false><<<dim3(gRows, 2), 256, smWab>>>(
            h1n, (const uint4*)(npb + NP_WAB), bch + l * 256, ab, N, 256);
        edge_kernel3<<<148, EDGE_THREADS, EDGE3_SMEM>>>(
            ea, srcp, dstp,
            (const uint4*)(wb + (size_t)l * WP_LAYER_ELEMS),
            be1 + l * 128, ab, agg, E);
        ln_kernel<<<(N + 7) / 8, 256>>>(agg, deg, bm2 + l * 128, lnw + l * 128,
                                        lnb + l * 128, xb, N);
        curx = xb;
    }
    ngemm<8, 8, false><<<dim3(gRows, 1), 256, smWf>>>(
        curx, (const uint4*)wfb, bf, (float*)d_out, N, 64);
}

// round 7
// speedup vs baseline: 1.0053x; 1.0053x over previous
#include <cuda_runtime.h>
#include <cuda_bf16.h>
#include <cstdint>

#define MAXN 50000
#define MAXE 800000
#define LLAYERS 3

// ================= helpers =================
__device__ __forceinline__ uint32_t packbf(float lo_v, float hi_v) {
    uint32_t r;
    asm("cvt.rn.satfinite.bf16x2.f32 %0, %1, %2;" : "=r"(r) : "f"(hi_v), "f"(lo_v));
    return r;
}
__device__ __forceinline__ float bfl(uint32_t p) { return __uint_as_float(p << 16); }
__device__ __forceinline__ float bfh(uint32_t p) { return __uint_as_float(p & 0xffff0000u); }

__device__ __forceinline__ void pack_hl(float v0, float v1, uint32_t& h, uint32_t& l) {
    h = packbf(v0, v1);
    l = packbf(v0 - bfl(h), v1 - bfh(h));
}

__device__ __forceinline__ void mma_bf16(float* c, const uint32_t* a, uint32_t b0, uint32_t b1) {
    asm volatile(
        "mma.sync.aligned.m16n8k16.row.col.f32.bf16.bf16.f32 "
        "{%0,%1,%2,%3}, {%4,%5,%6,%7}, {%8,%9}, {%0,%1,%2,%3};\n"
        : "+f"(c[0]), "+f"(c[1]), "+f"(c[2]), "+f"(c[3])
        : "r"(a[0]), "r"(a[1]), "r"(a[2]), "r"(a[3]), "r"(b0), "r"(b1));
}

// fragment-pair interleaved offset within a K-row: for element k,
// chunk j = k>>4; within chunk, groups of 4 elems {2g,2g+1,2g+8,2g+9}
// so that a lane's (b0,b1) 8-byte pair is contiguous (LDS.64).
__host__ __device__ __forceinline__ int wofs(int k) {
    int j = k >> 4, r = k & 15;
    return j * 16 + ((r & 7) >> 1) * 4 + ((r >> 3) << 1) + (r & 1);
}

// ================= scratch (static device globals) =================
__device__ float g_h1n[MAXN * 256];
__device__ float g_ab [MAXN * 256];
__device__ float g_x  [MAXN * 128];
__device__ float g_agg[MAXN * 128];
__device__ float g_deg[MAXN];
__device__ float g_Wab [LLAYERS * 256 * 256];
__device__ float g_Wc  [LLAYERS * 128 * 128];
__device__ float g_bch [LLAYERS * 256];   // [bc/2 | bc/2]
// per-layer packed bf16 transposed edge weights, 88064 elems / layer
#define WP_LAYER_ELEMS 88064
__device__ uint4 g_wpack[LLAYERS * WP_LAYER_ELEMS * 2 / 16];
// per-layer node weights: [W1hi 256x136][W1lo][WABhi 256x264][WABlo]
#define NP_LAYER_ELEMS 204800
#define NP_W1  0
#define NP_WAB 69632
__device__ uint4 g_wnode[LLAYERS * NP_LAYER_ELEMS * 2 / 16];
__device__ uint4 g_wf[2 * 64 * 136 * 2 / 16];

#define WO_WE1H 0
#define WO_WE1L 9216
#define WO_WCH  18432
#define WO_WCL  35840
#define WO_WM2H 53248
#define WO_WM2L 70656

// ================= fused weight-fuse kernel =================
// blocks [0,768): Wab ; [768,960): Wc ; [960,1008): bch
__global__ __launch_bounds__(256) void fuse_all(
    const float* __restrict__ Wn2, const float* __restrict__ Wm1,
    const float* __restrict__ We2, const float* __restrict__ bn2,
    const float* __restrict__ be2, const float* __restrict__ bm1,
    float* __restrict__ Wab, float* __restrict__ Wc, float* __restrict__ bch)
{
    int b = blockIdx.x, tid = threadIdx.x;
    if (b < 768) {
        int l = b >> 8;
        int idx = (b & 255) * 256 + tid;
        const float* wn2 = Wn2 + (size_t)l * 256 * 128;
        const float* wm1 = Wm1 + (size_t)l * 320 * 128;
        int k = idx >> 8, j = idx & 255;
        const float* wm = (j < 128) ? (wm1 + j) : (wm1 + 128 * 128 + (j - 128));
        float acc = 0.f;
        #pragma unroll 4
        for (int t = 0; t < 128; t++) acc += wn2[k * 128 + t] * wm[t * 128];
        Wab[(size_t)l * 65536 + idx] = acc;
    } else if (b < 960) {
        int lb = b - 768;
        int l = lb / 64;
        int idx = (lb % 64) * 256 + tid;
        const float* we2 = We2 + (size_t)l * 128 * 64;
        const float* wm1 = Wm1 + (size_t)l * 320 * 128;
        int k = idx >> 7, j = idx & 127;
        float acc = 0.f;
        #pragma unroll 4
        for (int t = 0; t < 64; t++) acc += we2[k * 64 + t] * wm1[(256 + t) * 128 + j];
        Wc[(size_t)l * 16384 + idx] = acc;
    } else {
        int lb = b - 960;
        int l = lb / 16;
        int lane = tid & 31;
        int j = (lb % 16) * 8 + (tid >> 5);
        const float* wm1 = Wm1 + (size_t)l * 320 * 128;
        const float* bn2l = bn2 + l * 128;
        const float* be2l = be2 + l * 64;
        float acc = 0.f;
        #pragma unroll
        for (int k = lane; k < 128; k += 32)
            acc += bn2l[k] * (wm1[k * 128 + j] + wm1[(128 + k) * 128 + j]);
        #pragma unroll
        for (int t = lane; t < 64; t += 32)
            acc += be2l[t] * wm1[(256 + t) * 128 + j];
        #pragma unroll
        for (int o = 16; o; o >>= 1) acc += __shfl_xor_sync(0xffffffffu, acc, o);
        if (lane == 0) {
            float half = 0.5f * (bm1[l * 128 + j] + acc);
            bch[l * 256 + j] = half;
            bch[l * 256 + 128 + j] = half;
        }
    }
}

// ================= fused bf16 hi/lo transpose prep kernel =================
__device__ __forceinline__ void splitw(float w, __nv_bfloat16* hi, __nv_bfloat16* lo, int o) {
    __nv_bfloat16 h = __float2bfloat16(w);
    hi[o] = h;
    lo[o] = __float2bfloat16(w - __bfloat162float(h));
}

// blocks: [0,96) we1t | [96,288) WcT | [288,480) Wm2T | [480,864) W1 | [864,1632) WAB | [1632,1664) Wf
__global__ __launch_bounds__(256) void prep_all(
    const float* __restrict__ We1, const float* __restrict__ WcG,
    const float* __restrict__ Wm2, const float* __restrict__ Wn1,
    const float* __restrict__ WabG, const float* __restrict__ Wf,
    __nv_bfloat16* __restrict__ wb, __nv_bfloat16* __restrict__ nbw,
    __nv_bfloat16* __restrict__ wfb)
{
    int b = blockIdx.x, tid = threadIdx.x;
    if (b < 96) {
        int l = b / 32;
        int idx = (b % 32) * 256 + tid;             // 8192 ; K=64, KP=72
        int n = idx >> 6, k = idx & 63;
        float w = We1[(size_t)l * 8192 + k * 128 + n];
        __nv_bfloat16* base = wb + (size_t)l * WP_LAYER_ELEMS;
        splitw(w, base + WO_WE1H, base + WO_WE1L, n * 72 + wofs(k));
    } else if (b < 288) {
        int lb = b - 96;
        int l = lb / 64;
        int idx = (lb % 64) * 256 + tid;            // 16384 ; K=128, KP=136
        int n = idx >> 7, k = idx & 127;
        float w = WcG[(size_t)l * 16384 + k * 128 + n];
        __nv_bfloat16* base = wb + (size_t)l * WP_LAYER_ELEMS;
        splitw(w, base + WO_WCH, base + WO_WCL, n * 136 + wofs(k));
    } else if (b < 480) {
        int lb = b - 288;
        int l = lb / 64;
        int idx = (lb % 64) * 256 + tid;            // 16384 ; K=128, KP=136
        int n = idx >> 7, k = idx & 127;
        float w = Wm2[(size_t)l * 16384 + k * 128 + n];
        __nv_bfloat16* base = wb + (size_t)l * WP_LAYER_ELEMS;
        splitw(w, base + WO_WM2H, base + WO_WM2L, n * 136 + wofs(k));
    } else if (b < 864) {
        int lb = b - 480;
        int l = lb / 128;
        int idx = (lb % 128) * 256 + tid;           // 32768 ; K=128,Nf=256,KP=136
        int n = idx & 255, k = idx >> 8;
        float w = Wn1[(size_t)l * 32768 + idx];
        __nv_bfloat16* base = nbw + (size_t)l * NP_LAYER_ELEMS + NP_W1;
        splitw(w, base, base + 256 * 136, n * 136 + wofs(k));
    } else if (b < 1632) {
        int lb = b - 864;
        int l = lb / 256;
        int idx = (lb % 256) * 256 + tid;           // 65536 ; K=256,Nf=256,KP=264
        int n = idx & 255, k = idx >> 8;
        float w = WabG[(size_t)l * 65536 + idx];
        __nv_bfloat16* base = nbw + (size_t)l * NP_LAYER_ELEMS + NP_WAB;
        splitw(w, base, base + 256 * 264, n * 264 + wofs(k));
    } else {
        int idx = (b - 1632) * 256 + tid;           // 8192 ; K=128,Nf=64,KP=136
        int n = idx & 63, k = idx >> 6;
        splitw(Wf[idx], wfb, wfb + 64 * 136, n * 136 + wofs(k));
    }
}

// ================= init (zero agg + deg) + degree =================
__global__ void zero_init(float* __restrict__ agg, float* __restrict__ deg, int N) {
    int i = blockIdx.x * blockDim.x + threadIdx.x;
    if (i < N * 32) ((float4*)agg)[i] = make_float4(0.f, 0.f, 0.f, 0.f);
    if (i < N) deg[i] = 0.f;
}

__global__ void deg_kernel(const int* __restrict__ dst, float* __restrict__ deg, int E) {
    int e = blockIdx.x * blockDim.x + threadIdx.x;
    if (e < E) atomicAdd(&deg[dst[e]], 1.f);
}

// ================= tensor-core node GEMM =================
template<int KCH, int NB, bool RELU>
__global__ __launch_bounds__(256) void ngemm(
    const float* __restrict__ A, const uint4* __restrict__ Wt,
    const float* __restrict__ bias, float* __restrict__ C, int M, int Nfull)
{
    constexpr int K = KCH * 16;
    constexpr int KP = K + 8;
    constexpr int NT = NB * 8;
    extern __shared__ char nsm[];
    __nv_bfloat16* Whs = (__nv_bfloat16*)nsm;
    __nv_bfloat16* Wls = Whs + NT * KP;
    float* bs = (float*)(Wls + NT * KP);

    int tid = threadIdx.x;
    int n0 = blockIdx.y * NT;
    {
        const uint4* hsrc = Wt + n0 * KP / 8;
        const uint4* lsrc = Wt + (Nfull * KP) / 8 + n0 * KP / 8;
        uint4* hdst = (uint4*)Whs;
        uint4* ldst = (uint4*)Wls;
        constexpr int CNT = NT * KP / 8;
        for (int i = tid; i < CNT; i += 256) { hdst[i] = hsrc[i]; ldst[i] = lsrc[i]; }
        if (tid < NT) bs[tid] = bias ? bias[n0 + tid] : 0.f;
    }
    __syncthreads();

    int lane = tid & 31, wid = tid >> 5;
    int qr = lane >> 2, qc = (lane & 3) * 2;
    int m0 = (blockIdx.x * 8 + wid) * 16;
    int r0 = m0 + qr, r1 = r0 + 8;
    bool v0 = r0 < M, v1 = r1 < M;
    const float* a0 = A + (size_t)(v0 ? r0 : 0) * K;
    const float* a1 = A + (size_t)(v1 ? r1 : 0) * K;

    float acc[NB][4];
    #pragma unroll
    for (int nb = 0; nb < NB; nb++) {
        acc[nb][0] = acc[nb][1] = acc[nb][2] = acc[nb][3] = 0.f;
    }

    #pragma unroll 2
    for (int j = 0; j < KCH; j++) {
        uint32_t Ah[4], Al[4];
        float2 x0 = *(const float2*)(a0 + 16 * j + qc);
        float2 x1 = *(const float2*)(a1 + 16 * j + qc);
        float2 x2 = *(const float2*)(a0 + 16 * j + qc + 8);
        float2 x3 = *(const float2*)(a1 + 16 * j + qc + 8);
        pack_hl(x0.x, x0.y, Ah[0], Al[0]);
        pack_hl(x1.x, x1.y, Ah[1], Al[1]);
        pack_hl(x2.x, x2.y, Ah[2], Al[2]);
        pack_hl(x3.x, x3.y, Ah[3], Al[3]);
        int fo = j * 16 + (qc >> 1) * 4;
        #pragma unroll
        for (int nb = 0; nb < NB; nb++) {
            const __nv_bfloat16* ph = Whs + (8 * nb + qr) * KP + fo;
            const __nv_bfloat16* pl = Wls + (8 * nb + qr) * KP + fo;
            uint2 bh = *(const uint2*)ph;
            uint2 bl = *(const uint2*)pl;
            mma_bf16(acc[nb], Ah, bh.x, bh.y);
            mma_bf16(acc[nb], Ah, bl.x, bl.y);
            mma_bf16(acc[nb], Al, bh.x, bh.y);
        }
    }

    #pragma unroll
    for (int nb = 0; nb < NB; nb++) {
        int col = 8 * nb + qc;
        float b0v = bs[col], b1v = bs[col + 1];
        float u0 = acc[nb][0] + b0v, u1 = acc[nb][1] + b1v;
        float u2 = acc[nb][2] + b0v, u3 = acc[nb][3] + b1v;
        if (RELU) {
            u0 = fmaxf(u0, 0.f); u1 = fmaxf(u1, 0.f);
            u2 = fmaxf(u2, 0.f); u3 = fmaxf(u3, 0.f);
        }
        if (v0) *(float2*)(C + (size_t)r0 * Nfull + n0 + col) = make_float2(u0, u1);
        if (v1) *(float2*)(C + (size_t)r1 * Nfull + n0 + col) = make_float2(u2, u3);
    }
}

// ================= mma.sync fused edge kernel (256 threads, LDS.64 layout) =================
#define EDGE3_SMEM (176128 + 1024)
#define EDGE_THREADS 256
#define EDGE_WARPS 8

template<int NC>
__device__ __forceinline__ void stage_mma(
    float acc[16][4], const uint32_t Ah[8][4], const uint32_t Al[8][4],
    const __nv_bfloat16* __restrict__ Wh, const __nv_bfloat16* __restrict__ Wl,
    int KP, int qr, int qc)
{
    #pragma unroll
    for (int j = 0; j < NC; j++) {
        int fo = j * 16 + (qc >> 1) * 4;
        #pragma unroll
        for (int nb = 0; nb < 16; nb++) {
            const __nv_bfloat16* ph = Wh + (8 * nb + qr) * KP + fo;
            const __nv_bfloat16* pl = Wl + (8 * nb + qr) * KP + fo;
            uint2 bh = *(const uint2*)ph;
            uint2 bl = *(const uint2*)pl;
            mma_bf16(acc[nb], Ah[j], bh.x, bh.y);
            mma_bf16(acc[nb], Ah[j], bl.x, bl.y);
            mma_bf16(acc[nb], Al[j], bh.x, bh.y);
        }
    }
}

__global__ __launch_bounds__(EDGE_THREADS) void edge_kernel3(
    const float* __restrict__ ea,
    const int* __restrict__ src, const int* __restrict__ dst,
    const uint4* __restrict__ wpack,
    const float* __restrict__ be1,
    const float* __restrict__ ab, float* __restrict__ agg, int E)
{
    extern __shared__ char smem[];
    __nv_bfloat16* W = (__nv_bfloat16*)smem;
    float* be1s = (float*)(smem + 176128);

    int tid = threadIdx.x;
    {
        uint4* s4 = (uint4*)smem;
        for (int i = tid; i < 11008; i += EDGE_THREADS) s4[i] = wpack[i];
        if (tid < 128) be1s[tid] = be1[tid];
    }
    __syncthreads();

    const __nv_bfloat16* We1h = W + WO_WE1H;
    const __nv_bfloat16* We1l = W + WO_WE1L;
    const __nv_bfloat16* Wch  = W + WO_WCH;
    const __nv_bfloat16* Wcl  = W + WO_WCL;
    const __nv_bfloat16* Wm2h = W + WO_WM2H;
    const __nv_bfloat16* Wm2l = W + WO_WM2L;

    int lane = tid & 31, wid = tid >> 5;
    int qr = lane >> 2;
    int qc = (lane & 3) * 2;

    int nG = (E + 15) >> 4;
    for (int g = blockIdx.x * EDGE_WARPS + wid; g < nG; g += gridDim.x * EDGE_WARPS) {
        int e0 = g << 4;
        int er0 = e0 + qr, er1 = er0 + 8;
        bool v0 = er0 < E, v1 = er1 < E;
        int ec0 = v0 ? er0 : 0, ec1 = v1 ? er1 : 0;
        int d0 = dst[ec0], d1 = dst[ec1];
        int s0 = src[ec0], s1 = src[ec1];

        uint32_t Ah[8][4], Al[8][4];
        float acc[16][4];

        #pragma unroll
        for (int j = 0; j < 4; j++) {
            const float* r0p = ea + (size_t)ec0 * 64 + 16 * j + qc;
            const float* r1p = ea + (size_t)ec1 * 64 + 16 * j + qc;
            float2 x0 = *(const float2*)r0p;
            float2 x1 = *(const float2*)r1p;
            float2 x2 = *(const float2*)(r0p + 8);
            float2 x3 = *(const float2*)(r1p + 8);
            pack_hl(x0.x, x0.y, Ah[j][0], Al[j][0]);
            pack_hl(x1.x, x1.y, Ah[j][1], Al[j][1]);
            pack_hl(x2.x, x2.y, Ah[j][2], Al[j][2]);
            pack_hl(x3.x, x3.y, Ah[j][3], Al[j][3]);
        }

        // S1
        #pragma unroll
        for (int nb = 0; nb < 16; nb++)
            #pragma unroll
            for (int q = 0; q < 4; q++) acc[nb][q] = 0.f;
        stage_mma<4>(acc, Ah, Al, We1h, We1l, 72, qr, qc);
        #pragma unroll
        for (int nb = 0; nb < 16; nb++) {
            int col = 8 * nb + qc;
            float b0 = be1s[col], b1 = be1s[col + 1];
            float u0 = fmaxf(acc[nb][0] + b0, 0.f);
            float u1 = fmaxf(acc[nb][1] + b1, 0.f);
            float u2 = fmaxf(acc[nb][2] + b0, 0.f);
            float u3 = fmaxf(acc[nb][3] + b1, 0.f);
            int j = nb >> 1, q = (nb & 1) * 2;
            pack_hl(u0, u1, Ah[j][q],     Al[j][q]);
            pack_hl(u2, u3, Ah[j][q + 1], Al[j][q + 1]);
        }

        // S2  (bc folded into ab via bch bias in the WAB gemm)
        #pragma unroll
        for (int nb = 0; nb < 16; nb++)
            #pragma unroll
            for (int q = 0; q < 4; q++) acc[nb][q] = 0.f;
        stage_mma<8>(acc, Ah, Al, Wch, Wcl, 136, qr, qc);
        {
            const float* a0p = ab + (size_t)d0 * 256;
            const float* a1p = ab + (size_t)d1 * 256;
            const float* b0p = ab + (size_t)s0 * 256 + 128;
            const float* b1p = ab + (size_t)s1 * 256 + 128;
            #pragma unroll
            for (int nb = 0; nb < 16; nb++) {
                int col = 8 * nb + qc;
                float2 ga0 = __ldg((const float2*)(a0p + col));
                float2 ga1 = __ldg((const float2*)(a1p + col));
                float2 gb0 = __ldg((const float2*)(b0p + col));
                float2 gb1 = __ldg((const float2*)(b1p + col));
                float u0 = fmaxf(acc[nb][0] + ga0.x + gb0.x, 0.f);
                float u1 = fmaxf(acc[nb][1] + ga0.y + gb0.y, 0.f);
                float u2 = fmaxf(acc[nb][2] + ga1.x + gb1.x, 0.f);
                float u3 = fmaxf(acc[nb][3] + ga1.y + gb1.y, 0.f);
                int j = nb >> 1, q = (nb & 1) * 2;
                pack_hl(u0, u1, Ah[j][q],     Al[j][q]);
                pack_hl(u2, u3, Ah[j][q + 1], Al[j][q + 1]);
            }
        }

        // S3
        #pragma unroll
        for (int nb = 0; nb < 16; nb++)
            #pragma unroll
            for (int q = 0; q < 4; q++) acc[nb][q] = 0.f;
        stage_mma<8>(acc, Ah, Al, Wm2h, Wm2l, 136, qr, qc);
        {
            float* g0 = agg + (size_t)d0 * 128;
            float* g1 = agg + (size_t)d1 * 128;
            #pragma unroll
            for (int nb = 0; nb < 16; nb++) {
                int col = 8 * nb + qc;
                if (v0)
                    asm volatile("red.global.add.v2.f32 [%0], {%1, %2};"
                                 :: "l"(g0 + col), "f"(acc[nb][0]), "f"(acc[nb][1]) : "memory");
                if (v1)
                    asm volatile("red.global.add.v2.f32 [%0], {%1, %2};"
                                 :: "l"(g1 + col), "f"(acc[nb][2]), "f"(acc[nb][3]) : "memory");
            }
        }
    }
}

// ================= LayerNorm + relu (+ agg re-zero for next layer) =================
__global__ void ln_kernel(float* __restrict__ agg, const float* __restrict__ deg,
                          const float* __restrict__ bm2, const float* __restrict__ lnw,
                          const float* __restrict__ lnb, float* __restrict__ xout, int N)
{
    int gwarp = (blockIdx.x * blockDim.x + threadIdx.x) >> 5;
    int lane = threadIdx.x & 31;
    if (gwarp >= N) return;
    float d = deg[gwarp];
    float inv = 1.f / fmaxf(d, 1.f);
    float add = (d > 0.f) ? 1.f : 0.f;
    float4 v = ((const float4*)agg)[(size_t)gwarp * 32 + lane];
    ((float4*)agg)[(size_t)gwarp * 32 + lane] = make_float4(0.f, 0.f, 0.f, 0.f);
    float4 b = ((const float4*)bm2)[lane];
    v.x = v.x * inv + add * b.x;
    v.y = v.y * inv + add * b.y;
    v.z = v.z * inv + add * b.z;
    v.w = v.w * inv + add * b.w;
    float s = v.x + v.y + v.z + v.w;
    #pragma unroll
    for (int o = 16; o; o >>= 1) s += __shfl_xor_sync(0xffffffffu, s, o);
    float mu = s * (1.f / 128.f);
    float d0 = v.x - mu, d1 = v.y - mu, d2 = v.z - mu, d3 = v.w - mu;
    float q = d0 * d0 + d1 * d1 + d2 * d2 + d3 * d3;
    #pragma unroll
    for (int o = 16; o; o >>= 1) q += __shfl_xor_sync(0xffffffffu, q, o);
    float rs = rsqrtf(q * (1.f / 128.f) + 1e-5f);
    float4 w = ((const float4*)lnw)[lane];
    float4 bb = ((const float4*)lnb)[lane];
    float4 o;
    o.x = fmaxf(d0 * rs * w.x + bb.x, 0.f);
    o.y = fmaxf(d1 * rs * w.y + bb.y, 0.f);
    o.z = fmaxf(d2 * rs * w.z + bb.z, 0.f);
    o.w = fmaxf(d3 * rs * w.w + bb.w, 0.f);
    ((float4*)xout)[(size_t)gwarp * 32 + lane] = o;
}

// ================= host =================
extern "C" void kernel_launch(void* const* d_in, const int* in_sizes, int n_in,
                              void* d_out, int out_size)
{
    const float* x    = (const float*)d_in[0];
    const float* ea   = (const float*)d_in[1];
    const int*   eidx = (const int*)  d_in[2];
    const float* Wn1  = (const float*)d_in[3];
    const float* bn1  = (const float*)d_in[4];
    const float* Wn2  = (const float*)d_in[5];
    const float* bn2  = (const float*)d_in[6];
    const float* We1  = (const float*)d_in[7];
    const float* be1  = (const float*)d_in[8];
    const float* We2  = (const float*)d_in[9];
    const float* be2  = (const float*)d_in[10];
    const float* Wm1  = (const float*)d_in[11];
    const float* bm1  = (const float*)d_in[12];
    const float* Wm2  = (const float*)d_in[13];
    const float* bm2  = (const float*)d_in[14];
    const float* lnw  = (const float*)d_in[15];
    const float* lnb  = (const float*)d_in[16];
    const float* Wf   = (const float*)d_in[17];
    const float* bf   = (const float*)d_in[18];

    int N = in_sizes[0] / 128;
    int E = in_sizes[1] / 64;
    const int* srcp = eidx;
    const int* dstp = eidx + E;

    float *h1n, *ab, *xb, *agg, *deg, *Wab, *Wc, *bch;
    uint4 *wpack, *wnode, *wf;
    cudaGetSymbolAddress((void**)&h1n, g_h1n);
    cudaGetSymbolAddress((void**)&ab,  g_ab);
    cudaGetSymbolAddress((void**)&xb,  g_x);
    cudaGetSymbolAddress((void**)&agg, g_agg);
    cudaGetSymbolAddress((void**)&deg, g_deg);
    cudaGetSymbolAddress((void**)&Wab, g_Wab);
    cudaGetSymbolAddress((void**)&Wc,  g_Wc);
    cudaGetSymbolAddress((void**)&bch, g_bch);
    cudaGetSymbolAddress((void**)&wpack, g_wpack);
    cudaGetSymbolAddress((void**)&wnode, g_wnode);
    cudaGetSymbolAddress((void**)&wf, g_wf);
    __nv_bfloat16* wb = (__nv_bfloat16*)wpack;
    __nv_bfloat16* nbw = (__nv_bfloat16*)wnode;
    __nv_bfloat16* wfb = (__nv_bfloat16*)wf;

    cudaFuncSetAttribute(edge_kernel3, cudaFuncAttributeMaxDynamicSharedMemorySize,
                         EDGE3_SMEM);
    int smW1  = 2 * 128 * 136 * 2 + 512;   // ngemm<8,16>
    int smWab = 2 * 128 * 264 * 2 + 512;   // ngemm<16,16>
    int smWf  = 2 * 64 * 136 * 2 + 256;    // ngemm<8,8>
    cudaFuncSetAttribute(ngemm<8, 16, true>,   cudaFuncAttributeMaxDynamicSharedMemorySize, smW1);
    cudaFuncSetAttribute(ngemm<16, 16, false>, cudaFuncAttributeMaxDynamicSharedMemorySize, smWab);
    cudaFuncSetAttribute(ngemm<8, 8, false>,   cudaFuncAttributeMaxDynamicSharedMemorySize, smWf);

    zero_init<<<(N * 32 + 255) / 256, 256>>>(agg, deg, N);
    deg_kernel<<<(E + 255) / 256, 256>>>(dstp, deg, E);
    fuse_all<<<1008, 256>>>(Wn2, Wm1, We2, bn2, be2, bm1, Wab, Wc, bch);
    prep_all<<<1664, 256>>>(We1, Wc, Wm2, Wn1, Wab, Wf, wb, nbw, wfb);

    const float* curx = x;
    int gRows = (N + 127) / 128;
    for (int l = 0; l < LLAYERS; l++) {
        __nv_bfloat16* npb = nbw + (size_t)l * NP_LAYER_ELEMS;
        ngemm<8, 16, true><<<dim3(gRows, 2), 256, smW1>>>(
            curx, (const uint4*)(npb + NP_W1), bn1 + l * 256, h1n, N, 256);
        ngemm<16, 16, false><<<dim3(gRows, 2), 256, smWab>>>(
            h1n, (const uint4*)(npb + NP_WAB), bch + l * 256, ab, N, 256);
        edge_kernel3<<<148, EDGE_THREADS, EDGE3_SMEM>>>(
            ea, srcp, dstp,
            (const uint4*)(wb + (size_t)l * WP_LAYER_ELEMS),
            be1 + l * 128, ab, agg, E);
        ln_kernel<<<(N + 7) / 8, 256>>>(agg, deg, bm2 + l * 128, lnw + l * 128,
                                        lnb + l * 128, xb, N);
        curx = xb;
    }
    ngemm<8, 8, false><<<dim3(gRows, 1), 256, smWf>>>(
        curx, (const uint4*)wfb, bf, (float*)d_out, N, 64);
}

// round 10
// speedup vs baseline: 1.2014x; 1.1950x over previous
#include <cuda_runtime.h>
#include <cuda_bf16.h>
#include <cstdint>

#define MAXN 50000
#define MAXE 800000
#define LLAYERS 3

// ================= helpers =================
__device__ __forceinline__ uint32_t packbf(float lo_v, float hi_v) {
    uint32_t r;
    asm("cvt.rn.satfinite.bf16x2.f32 %0, %1, %2;" : "=r"(r) : "f"(hi_v), "f"(lo_v));
    return r;
}
__device__ __forceinline__ float bfl(uint32_t p) { return __uint_as_float(p << 16); }
__device__ __forceinline__ float bfh(uint32_t p) { return __uint_as_float(p & 0xffff0000u); }

__device__ __forceinline__ void pack_hl(float v0, float v1, uint32_t& h, uint32_t& l) {
    h = packbf(v0, v1);
    l = packbf(v0 - bfl(h), v1 - bfh(h));
}

__device__ __forceinline__ void mma_bf16(float* c, const uint32_t* a, uint32_t b0, uint32_t b1) {
    asm volatile(
        "mma.sync.aligned.m16n8k16.row.col.f32.bf16.bf16.f32 "
        "{%0,%1,%2,%3}, {%4,%5,%6,%7}, {%8,%9}, {%0,%1,%2,%3};\n"
        : "+f"(c[0]), "+f"(c[1]), "+f"(c[2]), "+f"(c[3])
        : "r"(a[0]), "r"(a[1]), "r"(a[2]), "r"(a[3]), "r"(b0), "r"(b1));
}

// ================= scratch (static device globals) =================
__device__ float g_h1n[MAXN * 256];
__device__ float g_ab [MAXN * 256];
__device__ float g_x  [MAXN * 128];
__device__ float g_agg[MAXN * 128];
__device__ float g_Wab [LLAYERS * 256 * 256];
__device__ float g_Wc  [LLAYERS * 128 * 128];
__device__ float g_bch [LLAYERS * 256];   // [bc/2 | bc/2]
// sorted-edge machinery (small)
__device__ int g_hist[MAXN];
__device__ int g_cursor[MAXN];
__device__ int g_rowptr[MAXN + 1];
__device__ int g_bsum[256];
__device__ int g_perm[MAXE];
// per-layer packed bf16 transposed edge weights, 88064 elems / layer
#define WP_LAYER_ELEMS 88064
__device__ uint4 g_wpack[LLAYERS * WP_LAYER_ELEMS * 2 / 16];
// per-layer node weights: [W1hi 256x136][W1lo][WABhi 256x264][WABlo]
#define NP_LAYER_ELEMS 204800
#define NP_W1  0
#define NP_WAB 69632
__device__ uint4 g_wnode[LLAYERS * NP_LAYER_ELEMS * 2 / 16];
__device__ uint4 g_wf[2 * 64 * 136 * 2 / 16];

#define WO_WE1H 0
#define WO_WE1L 9216
#define WO_WCH  18432
#define WO_WCL  35840
#define WO_WM2H 53248
#define WO_WM2L 70656

// ================= fused weight-fuse kernel =================
// blocks [0,768): Wab ; [768,960): Wc ; [960,1008): bch
__global__ __launch_bounds__(256) void fuse_all(
    const float* __restrict__ Wn2, const float* __restrict__ Wm1,
    const float* __restrict__ We2, const float* __restrict__ bn2,
    const float* __restrict__ be2, const float* __restrict__ bm1,
    float* __restrict__ Wab, float* __restrict__ Wc, float* __restrict__ bch)
{
    int b = blockIdx.x, tid = threadIdx.x;
    if (b < 768) {
        int l = b >> 8;
        int idx = (b & 255) * 256 + tid;
        const float* wn2 = Wn2 + (size_t)l * 256 * 128;
        const float* wm1 = Wm1 + (size_t)l * 320 * 128;
        int k = idx >> 8, j = idx & 255;
        const float* wm = (j < 128) ? (wm1 + j) : (wm1 + 128 * 128 + (j - 128));
        float acc = 0.f;
        #pragma unroll 4
        for (int t = 0; t < 128; t++) acc += wn2[k * 128 + t] * wm[t * 128];
        Wab[(size_t)l * 65536 + idx] = acc;
    } else if (b < 960) {
        int lb = b - 768;
        int l = lb / 64;
        int idx = (lb % 64) * 256 + tid;
        const float* we2 = We2 + (size_t)l * 128 * 64;
        const float* wm1 = Wm1 + (size_t)l * 320 * 128;
        int k = idx >> 7, j = idx & 127;
        float acc = 0.f;
        #pragma unroll 4
        for (int t = 0; t < 64; t++) acc += we2[k * 64 + t] * wm1[(256 + t) * 128 + j];
        Wc[(size_t)l * 16384 + idx] = acc;
    } else {
        int lb = b - 960;
        int l = lb / 16;
        int lane = tid & 31;
        int j = (lb % 16) * 8 + (tid >> 5);
        const float* wm1 = Wm1 + (size_t)l * 320 * 128;
        const float* bn2l = bn2 + l * 128;
        const float* be2l = be2 + l * 64;
        float acc = 0.f;
        #pragma unroll
        for (int k = lane; k < 128; k += 32)
            acc += bn2l[k] * (wm1[k * 128 + j] + wm1[(128 + k) * 128 + j]);
        #pragma unroll
        for (int t = lane; t < 64; t += 32)
            acc += be2l[t] * wm1[(256 + t) * 128 + j];
        #pragma unroll
        for (int o = 16; o; o >>= 1) acc += __shfl_xor_sync(0xffffffffu, acc, o);
        if (lane == 0) {
            float half = 0.5f * (bm1[l * 128 + j] + acc);
            bch[l * 256 + j] = half;
            bch[l * 256 + 128 + j] = half;
        }
    }
}

// ================= fused bf16 hi/lo transpose prep kernel =================
__device__ __forceinline__ void splitw(float w, __nv_bfloat16* hi, __nv_bfloat16* lo, int o) {
    __nv_bfloat16 h = __float2bfloat16(w);
    hi[o] = h;
    lo[o] = __float2bfloat16(w - __bfloat162float(h));
}

// blocks: [0,96) we1t | [96,288) WcT | [288,480) Wm2T | [480,864) W1 | [864,1632) WAB | [1632,1664) Wf
__global__ __launch_bounds__(256) void prep_all(
    const float* __restrict__ We1, const float* __restrict__ WcG,
    const float* __restrict__ Wm2, const float* __restrict__ Wn1,
    const float* __restrict__ WabG, const float* __restrict__ Wf,
    __nv_bfloat16* __restrict__ wb, __nv_bfloat16* __restrict__ nbw,
    __nv_bfloat16* __restrict__ wfb)
{
    int b = blockIdx.x, tid = threadIdx.x;
    if (b < 96) {
        int l = b / 32;
        int idx = (b % 32) * 256 + tid;             // 8192 ; K=64, KP=72
        int n = idx >> 6, k = idx & 63;
        float w = We1[(size_t)l * 8192 + k * 128 + n];
        __nv_bfloat16* base = wb + (size_t)l * WP_LAYER_ELEMS;
        splitw(w, base + WO_WE1H, base + WO_WE1L, n * 72 + k);
    } else if (b < 288) {
        int lb = b - 96;
        int l = lb / 64;
        int idx = (lb % 64) * 256 + tid;            // 16384 ; K=128, KP=136
        int n = idx >> 7, k = idx & 127;
        float w = WcG[(size_t)l * 16384 + k * 128 + n];
        __nv_bfloat16* base = wb + (size_t)l * WP_LAYER_ELEMS;
        splitw(w, base + WO_WCH, base + WO_WCL, n * 136 + k);
    } else if (b < 480) {
        int lb = b - 288;
        int l = lb / 64;
        int idx = (lb % 64) * 256 + tid;            // 16384 ; K=128, KP=136
        int n = idx >> 7, k = idx & 127;
        float w = Wm2[(size_t)l * 16384 + k * 128 + n];
        __nv_bfloat16* base = wb + (size_t)l * WP_LAYER_ELEMS;
        splitw(w, base + WO_WM2H, base + WO_WM2L, n * 136 + k);
    } else if (b < 864) {
        int lb = b - 480;
        int l = lb / 128;
        int idx = (lb % 128) * 256 + tid;           // 32768 ; K=128,Nf=256,KP=136
        int n = idx & 255, k = idx >> 8;
        float w = Wn1[(size_t)l * 32768 + idx];
        __nv_bfloat16* base = nbw + (size_t)l * NP_LAYER_ELEMS + NP_W1;
        splitw(w, base, base + 256 * 136, n * 136 + k);
    } else if (b < 1632) {
        int lb = b - 864;
        int l = lb / 256;
        int idx = (lb % 256) * 256 + tid;           // 65536 ; K=256,Nf=256,KP=264
        int n = idx & 255, k = idx >> 8;
        float w = WabG[(size_t)l * 65536 + idx];
        __nv_bfloat16* base = nbw + (size_t)l * NP_LAYER_ELEMS + NP_WAB;
        splitw(w, base, base + 256 * 264, n * 264 + k);
    } else {
        int idx = (b - 1632) * 256 + tid;           // 8192 ; K=128,Nf=64,KP=136
        int n = idx & 63, k = idx >> 6;
        splitw(Wf[idx], wfb, wfb + 64 * 136, n * 136 + k);
    }
}

// ================= counting sort of edges by dst =================
__global__ void zero_init(int* __restrict__ hist, int* __restrict__ cursor,
                          float* __restrict__ agg, int N) {
    int i = blockIdx.x * blockDim.x + threadIdx.x;
    if (i < N) { hist[i] = 0; cursor[i] = 0; }
    if (i < N * 32) ((float4*)agg)[i] = make_float4(0.f, 0.f, 0.f, 0.f);
}

__global__ void hist_kernel(const int* __restrict__ dst, int* __restrict__ hist, int E) {
    int e = blockIdx.x * blockDim.x + threadIdx.x;
    if (e < E) atomicAdd(&hist[dst[e]], 1);
}

// per-block inclusive scan of 256 elems -> rowptr (inclusive), bsum[b] = block total
__global__ void scan1(const int* __restrict__ hist, int* __restrict__ rowptr,
                      int* __restrict__ bsum, int N) {
    __shared__ int s[256];
    int t = threadIdx.x, i = blockIdx.x * 256 + t;
    int v = (i < N) ? hist[i] : 0;
    s[t] = v;
    __syncthreads();
    #pragma unroll
    for (int o = 1; o < 256; o <<= 1) {
        int u = (t >= o) ? s[t - o] : 0;
        __syncthreads();
        s[t] += u;
        __syncthreads();
    }
    if (i < N) rowptr[i] = s[t];
    if (t == 255) bsum[blockIdx.x] = s[255];
}

// exclusive scan of block sums (nb <= 256), in place
__global__ void scan2(int* __restrict__ bsum, int nb) {
    __shared__ int s[256];
    int t = threadIdx.x;
    int orig = (t < nb) ? bsum[t] : 0;
    s[t] = orig;
    __syncthreads();
    #pragma unroll
    for (int o = 1; o < 256; o <<= 1) {
        int u = (t >= o) ? s[t - o] : 0;
        __syncthreads();
        s[t] += u;
        __syncthreads();
    }
    if (t < nb) bsum[t] = s[t] - orig;
}

// finalize exclusive rowptr
__global__ void scan3(int* __restrict__ rowptr, const int* __restrict__ hist,
                      const int* __restrict__ bsum, int N, int E) {
    int i = blockIdx.x * blockDim.x + threadIdx.x;
    if (i < N) rowptr[i] = rowptr[i] - hist[i] + bsum[i >> 8];
    if (i == N) rowptr[N] = E;
}

__global__ void scatter_kernel(const int* __restrict__ dst, const int* __restrict__ rowptr,
                               int* __restrict__ cursor, int* __restrict__ perm, int E) {
    int e = blockIdx.x * blockDim.x + threadIdx.x;
    if (e < E) {
        int d = dst[e];
        int pos = rowptr[d] + atomicAdd(&cursor[d], 1);
        perm[pos] = e;
    }
}

// ================= tensor-core node GEMM =================
template<int KCH, int NB, bool RELU>
__global__ __launch_bounds__(256) void ngemm(
    const float* __restrict__ A, const uint4* __restrict__ Wt,
    const float* __restrict__ bias, float* __restrict__ C, int M, int Nfull)
{
    constexpr int K = KCH * 16;
    constexpr int KP = K + 8;
    constexpr int NT = NB * 8;
    extern __shared__ char nsm[];
    __nv_bfloat16* Whs = (__nv_bfloat16*)nsm;
    __nv_bfloat16* Wls = Whs + NT * KP;
    float* bs = (float*)(Wls + NT * KP);

    int tid = threadIdx.x;
    int n0 = blockIdx.y * NT;
    {
        const uint4* hsrc = Wt + n0 * KP / 8;
        const uint4* lsrc = Wt + (Nfull * KP) / 8 + n0 * KP / 8;
        uint4* hdst = (uint4*)Whs;
        uint4* ldst = (uint4*)Wls;
        constexpr int CNT = NT * KP / 8;
        for (int i = tid; i < CNT; i += 256) { hdst[i] = hsrc[i]; ldst[i] = lsrc[i]; }
        if (tid < NT) bs[tid] = bias ? bias[n0 + tid] : 0.f;
    }
    __syncthreads();

    int lane = tid & 31, wid = tid >> 5;
    int qr = lane >> 2, qc = (lane & 3) * 2;
    int m0 = (blockIdx.x * 8 + wid) * 16;
    int r0 = m0 + qr, r1 = r0 + 8;
    bool v0 = r0 < M, v1 = r1 < M;
    const float* a0 = A + (size_t)(v0 ? r0 : 0) * K;
    const float* a1 = A + (size_t)(v1 ? r1 : 0) * K;

    float acc[NB][4];
    #pragma unroll
    for (int nb = 0; nb < NB; nb++) {
        acc[nb][0] = acc[nb][1] = acc[nb][2] = acc[nb][3] = 0.f;
    }

    #pragma unroll 2
    for (int j = 0; j < KCH; j++) {
        uint32_t Ah[4], Al[4];
        float2 x0 = *(const float2*)(a0 + 16 * j + qc);
        float2 x1 = *(const float2*)(a1 + 16 * j + qc);
        float2 x2 = *(const float2*)(a0 + 16 * j + qc + 8);
        float2 x3 = *(const float2*)(a1 + 16 * j + qc + 8);
        pack_hl(x0.x, x0.y, Ah[0], Al[0]);
        pack_hl(x1.x, x1.y, Ah[1], Al[1]);
        pack_hl(x2.x, x2.y, Ah[2], Al[2]);
        pack_hl(x3.x, x3.y, Ah[3], Al[3]);
        #pragma unroll
        for (int nb = 0; nb < NB; nb++) {
            const __nv_bfloat16* ph = Whs + (8 * nb + qr) * KP + 16 * j + qc;
            const __nv_bfloat16* pl = Wls + (8 * nb + qr) * KP + 16 * j + qc;
            uint32_t bh0 = *(const uint32_t*)ph;
            uint32_t bh1 = *(const uint32_t*)(ph + 8);
            uint32_t bl0 = *(const uint32_t*)pl;
            uint32_t bl1 = *(const uint32_t*)(pl + 8);
            mma_bf16(acc[nb], Ah, bh0, bh1);
            mma_bf16(acc[nb], Ah, bl0, bl1);
            mma_bf16(acc[nb], Al, bh0, bh1);
        }
    }

    #pragma unroll
    for (int nb = 0; nb < NB; nb++) {
        int col = 8 * nb + qc;
        float b0v = bs[col], b1v = bs[col + 1];
        float u0 = acc[nb][0] + b0v, u1 = acc[nb][1] + b1v;
        float u2 = acc[nb][2] + b0v, u3 = acc[nb][3] + b1v;
        if (RELU) {
            u0 = fmaxf(u0, 0.f); u1 = fmaxf(u1, 0.f);
            u2 = fmaxf(u2, 0.f); u3 = fmaxf(u3, 0.f);
        }
        if (v0) *(float2*)(C + (size_t)r0 * Nfull + n0 + col) = make_float2(u0, u1);
        if (v1) *(float2*)(C + (size_t)r1 * Nfull + n0 + col) = make_float2(u2, u3);
    }
}

// ================= mma.sync fused edge kernel (sorted, deduped atomics) =================
#define EDGE3_SMEM (176128 + 1024)
#define EDGE_THREADS 256
#define EDGE_WARPS 8

template<int NC>
__device__ __forceinline__ void stage_mma(
    float acc[16][4], const uint32_t Ah[8][4], const uint32_t Al[8][4],
    const __nv_bfloat16* __restrict__ Wh, const __nv_bfloat16* __restrict__ Wl,
    int KP, int qr, int qc)
{
    #pragma unroll
    for (int j = 0; j < NC; j++) {
        #pragma unroll
        for (int nb = 0; nb < 16; nb++) {
            const __nv_bfloat16* ph = Wh + (8 * nb + qr) * KP + 16 * j + qc;
            const __nv_bfloat16* pl = Wl + (8 * nb + qr) * KP + 16 * j + qc;
            uint32_t bh0 = *(const uint32_t*)ph;
            uint32_t bh1 = *(const uint32_t*)(ph + 8);
            uint32_t bl0 = *(const uint32_t*)pl;
            uint32_t bl1 = *(const uint32_t*)(pl + 8);
            mma_bf16(acc[nb], Ah[j], bh0, bh1);
            mma_bf16(acc[nb], Ah[j], bl0, bl1);
            mma_bf16(acc[nb], Al[j], bh0, bh1);
        }
    }
}

__global__ __launch_bounds__(EDGE_THREADS) void edge_kernel5(
    const float* __restrict__ ea,
    const int* __restrict__ src, const int* __restrict__ dst,
    const int* __restrict__ perm,
    const uint4* __restrict__ wpack,
    const float* __restrict__ be1,
    const float* __restrict__ ab, float* __restrict__ agg, int E)
{
    extern __shared__ char smem[];
    __nv_bfloat16* W = (__nv_bfloat16*)smem;
    float* be1s = (float*)(smem + 176128);

    int tid = threadIdx.x;
    {
        uint4* s4 = (uint4*)smem;
        for (int i = tid; i < 11008; i += EDGE_THREADS) s4[i] = wpack[i];
        if (tid < 128) be1s[tid] = be1[tid];
    }
    __syncthreads();

    const __nv_bfloat16* We1h = W + WO_WE1H;
    const __nv_bfloat16* We1l = W + WO_WE1L;
    const __nv_bfloat16* Wch  = W + WO_WCH;
    const __nv_bfloat16* Wcl  = W + WO_WCL;
    const __nv_bfloat16* Wm2h = W + WO_WM2H;
    const __nv_bfloat16* Wm2l = W + WO_WM2L;

    int lane = tid & 31, wid = tid >> 5;
    int qr = lane >> 2;
    int qc = (lane & 3) * 2;

    int nG = (E + 15) >> 4;
    for (int g = blockIdx.x * EDGE_WARPS + wid; g < nG; g += gridDim.x * EDGE_WARPS) {
        int p0 = g << 4;
        int pr0 = p0 + qr, pr1 = pr0 + 8;
        bool v0 = pr0 < E, v1 = pr1 < E;
        int ec0 = v0 ? perm[pr0] : 0, ec1 = v1 ? perm[pr1] : 0;
        int d0 = dst[ec0], d1 = dst[ec1];
        int s0 = src[ec0], s1 = src[ec1];

        uint32_t Ah[8][4], Al[8][4];
        float acc[16][4];

        #pragma unroll
        for (int j = 0; j < 4; j++) {
            const float* r0p = ea + (size_t)ec0 * 64 + 16 * j + qc;
            const float* r1p = ea + (size_t)ec1 * 64 + 16 * j + qc;
            float2 x0 = *(const float2*)r0p;
            float2 x1 = *(const float2*)r1p;
            float2 x2 = *(const float2*)(r0p + 8);
            float2 x3 = *(const float2*)(r1p + 8);
            pack_hl(x0.x, x0.y, Ah[j][0], Al[j][0]);
            pack_hl(x1.x, x1.y, Ah[j][1], Al[j][1]);
            pack_hl(x2.x, x2.y, Ah[j][2], Al[j][2]);
            pack_hl(x3.x, x3.y, Ah[j][3], Al[j][3]);
        }

        // S1
        #pragma unroll
        for (int nb = 0; nb < 16; nb++)
            #pragma unroll
            for (int q = 0; q < 4; q++) acc[nb][q] = 0.f;
        stage_mma<4>(acc, Ah, Al, We1h, We1l, 72, qr, qc);
        #pragma unroll
        for (int nb = 0; nb < 16; nb++) {
            int col = 8 * nb + qc;
            float b0 = be1s[col], b1 = be1s[col + 1];
            float u0 = fmaxf(acc[nb][0] + b0, 0.f);
            float u1 = fmaxf(acc[nb][1] + b1, 0.f);
            float u2 = fmaxf(acc[nb][2] + b0, 0.f);
            float u3 = fmaxf(acc[nb][3] + b1, 0.f);
            int j = nb >> 1, q = (nb & 1) * 2;
            pack_hl(u0, u1, Ah[j][q],     Al[j][q]);
            pack_hl(u2, u3, Ah[j][q + 1], Al[j][q + 1]);
        }

        // S2  (bc folded into ab via bch bias in the WAB gemm)
        #pragma unroll
        for (int nb = 0; nb < 16; nb++)
            #pragma unroll
            for (int q = 0; q < 4; q++) acc[nb][q] = 0.f;
        stage_mma<8>(acc, Ah, Al, Wch, Wcl, 136, qr, qc);
        {
            const float* a0p = ab + (size_t)d0 * 256;
            const float* a1p = ab + (size_t)d1 * 256;
            const float* b0p = ab + (size_t)s0 * 256 + 128;
            const float* b1p = ab + (size_t)s1 * 256 + 128;
            #pragma unroll
            for (int nb = 0; nb < 16; nb++) {
                int col = 8 * nb + qc;
                float2 ga0 = *(const float2*)(a0p + col);
                float2 ga1 = *(const float2*)(a1p + col);
                float2 gb0 = *(const float2*)(b0p + col);
                float2 gb1 = *(const float2*)(b1p + col);
                float u0 = fmaxf(acc[nb][0] + ga0.x + gb0.x, 0.f);
                float u1 = fmaxf(acc[nb][1] + ga0.y + gb0.y, 0.f);
                float u2 = fmaxf(acc[nb][2] + ga1.x + gb1.x, 0.f);
                float u3 = fmaxf(acc[nb][3] + ga1.y + gb1.y, 0.f);
                int j = nb >> 1, q = (nb & 1) * 2;
                pack_hl(u0, u1, Ah[j][q],     Al[j][q]);
                pack_hl(u2, u3, Ah[j][q + 1], Al[j][q + 1]);
            }
        }

        // S3 + deduped atomic scatter (sorted dst => rows qr and qr+8 often share dst)
        #pragma unroll
        for (int nb = 0; nb < 16; nb++)
            #pragma unroll
            for (int q = 0; q < 4; q++) acc[nb][q] = 0.f;
        stage_mma<8>(acc, Ah, Al, Wm2h, Wm2l, 136, qr, qc);
        {
            float* g0 = agg + (size_t)d0 * 128;
            float* g1 = agg + (size_t)d1 * 128;
            bool same = v1 && (d0 == d1);
            #pragma unroll
            for (int nb = 0; nb < 16; nb++) {
                int col = 8 * nb + qc;
                if (same) {
                    asm volatile("red.global.add.v2.f32 [%0], {%1, %2};"
                                 :: "l"(g0 + col),
                                    "f"(acc[nb][0] + acc[nb][2]),
                                    "f"(acc[nb][1] + acc[nb][3]) : "memory");
                } else {
                    if (v0)
                        asm volatile("red.global.add.v2.f32 [%0], {%1, %2};"
                                     :: "l"(g0 + col), "f"(acc[nb][0]), "f"(acc[nb][1]) : "memory");
                    if (v1)
                        asm volatile("red.global.add.v2.f32 [%0], {%1, %2};"
                                     :: "l"(g1 + col), "f"(acc[nb][2]), "f"(acc[nb][3]) : "memory");
                }
            }
        }
    }
}

// ================= LayerNorm + relu (+ agg re-zero for next layer) =================
__global__ void ln_kernel(float* __restrict__ agg, const int* __restrict__ rowptr,
                          const float* __restrict__ bm2, const float* __restrict__ lnw,
                          const float* __restrict__ lnb, float* __restrict__ xout, int N)
{
    int node = (blockIdx.x * blockDim.x + threadIdx.x) >> 5;
    int lane = threadIdx.x & 31;
    if (node >= N) return;
    float d = (float)(rowptr[node + 1] - rowptr[node]);
    float inv = 1.f / fmaxf(d, 1.f);
    float add = (d > 0.f) ? 1.f : 0.f;
    float4 v = ((const float4*)agg)[(size_t)node * 32 + lane];
    ((float4*)agg)[(size_t)node * 32 + lane] = make_float4(0.f, 0.f, 0.f, 0.f);
    float4 b = ((const float4*)bm2)[lane];
    v.x = v.x * inv + add * b.x;
    v.y = v.y * inv + add * b.y;
    v.z = v.z * inv + add * b.z;
    v.w = v.w * inv + add * b.w;
    float s = v.x + v.y + v.z + v.w;
    #pragma unroll
    for (int o = 16; o; o >>= 1) s += __shfl_xor_sync(0xffffffffu, s, o);
    float mu = s * (1.f / 128.f);
    float d0 = v.x - mu, d1 = v.y - mu, d2 = v.z - mu, d3 = v.w - mu;
    float q = d0 * d0 + d1 * d1 + d2 * d2 + d3 * d3;
    #pragma unroll
    for (int o = 16; o; o >>= 1) q += __shfl_xor_sync(0xffffffffu, q, o);
    float rs = rsqrtf(q * (1.f / 128.f) + 1e-5f);
    float4 w = ((const float4*)lnw)[lane];
    float4 bb = ((const float4*)lnb)[lane];
    float4 o;
    o.x = fmaxf(d0 * rs * w.x + bb.x, 0.f);
    o.y = fmaxf(d1 * rs * w.y + bb.y, 0.f);
    o.z = fmaxf(d2 * rs * w.z + bb.z, 0.f);
    o.w = fmaxf(d3 * rs * w.w + bb.w, 0.f);
    ((float4*)xout)[(size_t)node * 32 + lane] = o;
}

// ================= host =================
extern "C" void kernel_launch(void* const* d_in, const int* in_sizes, int n_in,
                              void* d_out, int out_size)
{
    const float* x    = (const float*)d_in[0];
    const float* ea   = (const float*)d_in[1];
    const int*   eidx = (const int*)  d_in[2];
    const float* Wn1  = (const float*)d_in[3];
    const float* bn1  = (const float*)d_in[4];
    const float* Wn2  = (const float*)d_in[5];
    const float* bn2  = (const float*)d_in[6];
    const float* We1  = (const float*)d_in[7];
    const float* be1  = (const float*)d_in[8];
    const float* We2  = (const float*)d_in[9];
    const float* be2  = (const float*)d_in[10];
    const float* Wm1  = (const float*)d_in[11];
    const float* bm1  = (const float*)d_in[12];
    const float* Wm2  = (const float*)d_in[13];
    const float* bm2  = (const float*)d_in[14];
    const float* lnw  = (const float*)d_in[15];
    const float* lnb  = (const float*)d_in[16];
    const float* Wf   = (const float*)d_in[17];
    const float* bf   = (const float*)d_in[18];

    int N = in_sizes[0] / 128;
    int E = in_sizes[1] / 64;
    const int* srcp = eidx;
    const int* dstp = eidx + E;

    float *h1n, *ab, *xb, *agg, *Wab, *Wc, *bch;
    int *hist, *cursor, *rowptr, *bsum, *perm;
    uint4 *wpack, *wnode, *wf;
    cudaGetSymbolAddress((void**)&h1n, g_h1n);
    cudaGetSymbolAddress((void**)&ab,  g_ab);
    cudaGetSymbolAddress((void**)&xb,  g_x);
    cudaGetSymbolAddress((void**)&agg, g_agg);
    cudaGetSymbolAddress((void**)&Wab, g_Wab);
    cudaGetSymbolAddress((void**)&Wc,  g_Wc);
    cudaGetSymbolAddress((void**)&bch, g_bch);
    cudaGetSymbolAddress((void**)&hist, g_hist);
    cudaGetSymbolAddress((void**)&cursor, g_cursor);
    cudaGetSymbolAddress((void**)&rowptr, g_rowptr);
    cudaGetSymbolAddress((void**)&bsum, g_bsum);
    cudaGetSymbolAddress((void**)&perm, g_perm);
    cudaGetSymbolAddress((void**)&wpack, g_wpack);
    cudaGetSymbolAddress((void**)&wnode, g_wnode);
    cudaGetSymbolAddress((void**)&wf, g_wf);
    __nv_bfloat16* wb = (__nv_bfloat16*)wpack;
    __nv_bfloat16* nbw = (__nv_bfloat16*)wnode;
    __nv_bfloat16* wfb = (__nv_bfloat16*)wf;

    cudaFuncSetAttribute(edge_kernel5, cudaFuncAttributeMaxDynamicSharedMemorySize,
                         EDGE3_SMEM);
    int smW1  = 2 * 128 * 136 * 2 + 512;   // ngemm<8,16>
    int smWab = 2 * 128 * 264 * 2 + 512;   // ngemm<16,16>
    int smWf  = 2 * 64 * 136 * 2 + 256;    // ngemm<8,8>
    cudaFuncSetAttribute(ngemm<8, 16, true>,   cudaFuncAttributeMaxDynamicSharedMemorySize, smW1);
    cudaFuncSetAttribute(ngemm<16, 16, false>, cudaFuncAttributeMaxDynamicSharedMemorySize, smWab);
    cudaFuncSetAttribute(ngemm<8, 8, false>,   cudaFuncAttributeMaxDynamicSharedMemorySize, smWf);

    int nBlk = (N + 255) / 256;   // 196 for N=50000 (<=256 required by scan2)
    zero_init<<<(N * 32 + 255) / 256, 256>>>(hist, cursor, agg, N);
    hist_kernel<<<(E + 255) / 256, 256>>>(dstp, hist, E);
    scan1<<<nBlk, 256>>>(hist, rowptr, bsum, N);
    scan2<<<1, 256>>>(bsum, nBlk);
    scan3<<<(N + 256) / 256, 256>>>(rowptr, hist, bsum, N, E);
    scatter_kernel<<<(E + 255) / 256, 256>>>(dstp, rowptr, cursor, perm, E);
    fuse_all<<<1008, 256>>>(Wn2, Wm1, We2, bn2, be2, bm1, Wab, Wc, bch);
    prep_all<<<1664, 256>>>(We1, Wc, Wm2, Wn1, Wab, Wf, wb, nbw, wfb);

    const float* curx = x;
    int gRows = (N + 127) / 128;
    for (int l = 0; l < LLAYERS; l++) {
        __nv_bfloat16* npb = nbw + (size_t)l * NP_LAYER_ELEMS;
        ngemm<8, 16, true><<<dim3(gRows, 2), 256, smW1>>>(
            curx, (const uint4*)(npb + NP_W1), bn1 + l * 256, h1n, N, 256);
        ngemm<16, 16, false><<<dim3(gRows, 2), 256, smWab>>>(
            h1n, (const uint4*)(npb + NP_WAB), bch + l * 256, ab, N, 256);
        edge_kernel5<<<148, EDGE_THREADS, EDGE3_SMEM>>>(
            ea, srcp, dstp, perm,
            (const uint4*)(wb + (size_t)l * WP_LAYER_ELEMS),
            be1 + l * 128, ab, agg, E);
        ln_kernel<<<(N + 7) / 8, 256>>>(agg, rowptr, bm2 + l * 128, lnw + l * 128,
                                        lnb + l * 128, xb, N);
        curx = xb;
    }
    ngemm<8, 8, false><<<dim3(gRows, 1), 256, smWf>>>(
        curx, (const uint4*)wfb, bf, (float*)d_out, N, 64);
}

// round 11
// speedup vs baseline: 1.2211x; 1.0164x over previous
#include <cuda_runtime.h>
#include <cuda_bf16.h>
#include <cuda_fp16.h>
#include <cstdint>

#define MAXN 50000
#define MAXE 800000
#define LLAYERS 3

// ================= helpers =================
// pack two floats to half2: hi_v -> upper 16, lo_v -> lower 16
__device__ __forceinline__ uint32_t packh(float lo_v, float hi_v) {
    uint32_t r;
    asm("cvt.rn.f16x2.f32 %0, %1, %2;" : "=r"(r) : "f"(hi_v), "f"(lo_v));
    return r;
}

__device__ __forceinline__ void mma_f16(float* c, const uint32_t* a, uint32_t b0, uint32_t b1) {
    asm volatile(
        "mma.sync.aligned.m16n8k16.row.col.f32.f16.f16.f32 "
        "{%0,%1,%2,%3}, {%4,%5,%6,%7}, {%8,%9}, {%0,%1,%2,%3};\n"
        : "+f"(c[0]), "+f"(c[1]), "+f"(c[2]), "+f"(c[3])
        : "r"(a[0]), "r"(a[1]), "r"(a[2]), "r"(a[3]), "r"(b0), "r"(b1));
}

// ================= scratch (static device globals) =================
__device__ float g_h1n[MAXN * 256];
__device__ float g_ab [MAXN * 256];
__device__ float g_x  [MAXN * 128];
__device__ float g_agg[MAXN * 128];
__device__ float g_Wab [LLAYERS * 256 * 256];
__device__ float g_Wc  [LLAYERS * 128 * 128];
__device__ float g_bch [LLAYERS * 256];   // [bc/2 | bc/2]
// sorted-edge machinery (small)
__device__ int g_hist[MAXN];
__device__ int g_cursor[MAXN];
__device__ int g_rowptr[MAXN + 1];
__device__ int g_bsum[256];
__device__ int g_perm[MAXE];
// per-layer packed fp16 transposed edge weights, 88064 elems / layer
#define WP_LAYER_ELEMS 88064
__device__ uint4 g_wpack[LLAYERS * WP_LAYER_ELEMS * 2 / 16];
// per-layer node weights: [W1hi 256x136][W1lo][WABhi 256x264][WABlo]
#define NP_LAYER_ELEMS 204800
#define NP_W1  0
#define NP_WAB 69632
__device__ uint4 g_wnode[LLAYERS * NP_LAYER_ELEMS * 2 / 16];
__device__ uint4 g_wf[2 * 64 * 136 * 2 / 16];

#define WO_WE1H 0
#define WO_WE1L 9216
#define WO_WCH  18432
#define WO_WCL  35840
#define WO_WM2H 53248
#define WO_WM2L 70656

// ================= fused weight-fuse kernel =================
// blocks [0,768): Wab ; [768,960): Wc ; [960,1008): bch
__global__ __launch_bounds__(256) void fuse_all(
    const float* __restrict__ Wn2, const float* __restrict__ Wm1,
    const float* __restrict__ We2, const float* __restrict__ bn2,
    const float* __restrict__ be2, const float* __restrict__ bm1,
    float* __restrict__ Wab, float* __restrict__ Wc, float* __restrict__ bch)
{
    int b = blockIdx.x, tid = threadIdx.x;
    if (b < 768) {
        int l = b >> 8;
        int idx = (b & 255) * 256 + tid;
        const float* wn2 = Wn2 + (size_t)l * 256 * 128;
        const float* wm1 = Wm1 + (size_t)l * 320 * 128;
        int k = idx >> 8, j = idx & 255;
        const float* wm = (j < 128) ? (wm1 + j) : (wm1 + 128 * 128 + (j - 128));
        float acc = 0.f;
        #pragma unroll 4
        for (int t = 0; t < 128; t++) acc += wn2[k * 128 + t] * wm[t * 128];
        Wab[(size_t)l * 65536 + idx] = acc;
    } else if (b < 960) {
        int lb = b - 768;
        int l = lb / 64;
        int idx = (lb % 64) * 256 + tid;
        const float* we2 = We2 + (size_t)l * 128 * 64;
        const float* wm1 = Wm1 + (size_t)l * 320 * 128;
        int k = idx >> 7, j = idx & 127;
        float acc = 0.f;
        #pragma unroll 4
        for (int t = 0; t < 64; t++) acc += we2[k * 64 + t] * wm1[(256 + t) * 128 + j];
        Wc[(size_t)l * 16384 + idx] = acc;
    } else {
        int lb = b - 960;
        int l = lb / 16;
        int lane = tid & 31;
        int j = (lb % 16) * 8 + (tid >> 5);
        const float* wm1 = Wm1 + (size_t)l * 320 * 128;
        const float* bn2l = bn2 + l * 128;
        const float* be2l = be2 + l * 64;
        float acc = 0.f;
        #pragma unroll
        for (int k = lane; k < 128; k += 32)
            acc += bn2l[k] * (wm1[k * 128 + j] + wm1[(128 + k) * 128 + j]);
        #pragma unroll
        for (int t = lane; t < 64; t += 32)
            acc += be2l[t] * wm1[(256 + t) * 128 + j];
        #pragma unroll
        for (int o = 16; o; o >>= 1) acc += __shfl_xor_sync(0xffffffffu, acc, o);
        if (lane == 0) {
            float half = 0.5f * (bm1[l * 128 + j] + acc);
            bch[l * 256 + j] = half;
            bch[l * 256 + 128 + j] = half;
        }
    }
}

// ================= fused fp16 hi/lo transpose prep kernel =================
__device__ __forceinline__ void splitw(float w, __half* hi, __half* lo, int o) {
    __half h = __float2half_rn(w);
    hi[o] = h;
    lo[o] = __float2half_rn(w - __half2float(h));
}

// blocks: [0,96) we1t | [96,288) WcT | [288,480) Wm2T | [480,864) W1 | [864,1632) WAB | [1632,1664) Wf
__global__ __launch_bounds__(256) void prep_all(
    const float* __restrict__ We1, const float* __restrict__ WcG,
    const float* __restrict__ Wm2, const float* __restrict__ Wn1,
    const float* __restrict__ WabG, const float* __restrict__ Wf,
    __half* __restrict__ wb, __half* __restrict__ nbw,
    __half* __restrict__ wfb)
{
    int b = blockIdx.x, tid = threadIdx.x;
    if (b < 96) {
        int l = b / 32;
        int idx = (b % 32) * 256 + tid;             // 8192 ; K=64, KP=72
        int n = idx >> 6, k = idx & 63;
        float w = We1[(size_t)l * 8192 + k * 128 + n];
        __half* base = wb + (size_t)l * WP_LAYER_ELEMS;
        splitw(w, base + WO_WE1H, base + WO_WE1L, n * 72 + k);
    } else if (b < 288) {
        int lb = b - 96;
        int l = lb / 64;
        int idx = (lb % 64) * 256 + tid;            // 16384 ; K=128, KP=136
        int n = idx >> 7, k = idx & 127;
        float w = WcG[(size_t)l * 16384 + k * 128 + n];
        __half* base = wb + (size_t)l * WP_LAYER_ELEMS;
        splitw(w, base + WO_WCH, base + WO_WCL, n * 136 + k);
    } else if (b < 480) {
        int lb = b - 288;
        int l = lb / 64;
        int idx = (lb % 64) * 256 + tid;            // 16384 ; K=128, KP=136
        int n = idx >> 7, k = idx & 127;
        float w = Wm2[(size_t)l * 16384 + k * 128 + n];
        __half* base = wb + (size_t)l * WP_LAYER_ELEMS;
        splitw(w, base + WO_WM2H, base + WO_WM2L, n * 136 + k);
    } else if (b < 864) {
        int lb = b - 480;
        int l = lb / 128;
        int idx = (lb % 128) * 256 + tid;           // 32768 ; K=128,Nf=256,KP=136
        int n = idx & 255, k = idx >> 8;
        float w = Wn1[(size_t)l * 32768 + idx];
        __half* base = nbw + (size_t)l * NP_LAYER_ELEMS + NP_W1;
        splitw(w, base, base + 256 * 136, n * 136 + k);
    } else if (b < 1632) {
        int lb = b - 864;
        int l = lb / 256;
        int idx = (lb % 256) * 256 + tid;           // 65536 ; K=256,Nf=256,KP=264
        int n = idx & 255, k = idx >> 8;
        float w = WabG[(size_t)l * 65536 + idx];
        __half* base = nbw + (size_t)l * NP_LAYER_ELEMS + NP_WAB;
        splitw(w, base, base + 256 * 264, n * 264 + k);
    } else {
        int idx = (b - 1632) * 256 + tid;           // 8192 ; K=128,Nf=64,KP=136
        int n = idx & 63, k = idx >> 6;
        splitw(Wf[idx], wfb, wfb + 64 * 136, n * 136 + k);
    }
}

// ================= counting sort of edges by dst =================
__global__ void zero_init(int* __restrict__ hist, int* __restrict__ cursor,
                          float* __restrict__ agg, int N) {
    int i = blockIdx.x * blockDim.x + threadIdx.x;
    if (i < N) { hist[i] = 0; cursor[i] = 0; }
    if (i < N * 32) ((float4*)agg)[i] = make_float4(0.f, 0.f, 0.f, 0.f);
}

__global__ void hist_kernel(const int* __restrict__ dst, int* __restrict__ hist, int E) {
    int e = blockIdx.x * blockDim.x + threadIdx.x;
    if (e < E) atomicAdd(&hist[dst[e]], 1);
}

// per-block inclusive scan of 256 elems -> rowptr (inclusive), bsum[b] = block total
__global__ void scan1(const int* __restrict__ hist, int* __restrict__ rowptr,
                      int* __restrict__ bsum, int N) {
    __shared__ int s[256];
    int t = threadIdx.x, i = blockIdx.x * 256 + t;
    int v = (i < N) ? hist[i] : 0;
    s[t] = v;
    __syncthreads();
    #pragma unroll
    for (int o = 1; o < 256; o <<= 1) {
        int u = (t >= o) ? s[t - o] : 0;
        __syncthreads();
        s[t] += u;
        __syncthreads();
    }
    if (i < N) rowptr[i] = s[t];
    if (t == 255) bsum[blockIdx.x] = s[255];
}

// exclusive scan of block sums (nb <= 256), in place
__global__ void scan2(int* __restrict__ bsum, int nb) {
    __shared__ int s[256];
    int t = threadIdx.x;
    int orig = (t < nb) ? bsum[t] : 0;
    s[t] = orig;
    __syncthreads();
    #pragma unroll
    for (int o = 1; o < 256; o <<= 1) {
        int u = (t >= o) ? s[t - o] : 0;
        __syncthreads();
        s[t] += u;
        __syncthreads();
    }
    if (t < nb) bsum[t] = s[t] - orig;
}

// finalize exclusive rowptr
__global__ void scan3(int* __restrict__ rowptr, const int* __restrict__ hist,
                      const int* __restrict__ bsum, int N, int E) {
    int i = blockIdx.x * blockDim.x + threadIdx.x;
    if (i < N) rowptr[i] = rowptr[i] - hist[i] + bsum[i >> 8];
    if (i == N) rowptr[N] = E;
}

__global__ void scatter_kernel(const int* __restrict__ dst, const int* __restrict__ rowptr,
                               int* __restrict__ cursor, int* __restrict__ perm, int E) {
    int e = blockIdx.x * blockDim.x + threadIdx.x;
    if (e < E) {
        int d = dst[e];
        int pos = rowptr[d] + atomicAdd(&cursor[d], 1);
        perm[pos] = e;
    }
}

// ================= tensor-core node GEMM (fp16 2-term) =================
template<int KCH, int NB, bool RELU>
__global__ __launch_bounds__(256) void ngemm(
    const float* __restrict__ A, const uint4* __restrict__ Wt,
    const float* __restrict__ bias, float* __restrict__ C, int M, int Nfull)
{
    constexpr int K = KCH * 16;
    constexpr int KP = K + 8;
    constexpr int NT = NB * 8;
    extern __shared__ char nsm[];
    __half* Whs = (__half*)nsm;
    __half* Wls = Whs + NT * KP;
    float* bs = (float*)(Wls + NT * KP);

    int tid = threadIdx.x;
    int n0 = blockIdx.y * NT;
    {
        const uint4* hsrc = Wt + n0 * KP / 8;
        const uint4* lsrc = Wt + (Nfull * KP) / 8 + n0 * KP / 8;
        uint4* hdst = (uint4*)Whs;
        uint4* ldst = (uint4*)Wls;
        constexpr int CNT = NT * KP / 8;
        for (int i = tid; i < CNT; i += 256) { hdst[i] = hsrc[i]; ldst[i] = lsrc[i]; }
        if (tid < NT) bs[tid] = bias ? bias[n0 + tid] : 0.f;
    }
    __syncthreads();

    int lane = tid & 31, wid = tid >> 5;
    int qr = lane >> 2, qc = (lane & 3) * 2;
    int m0 = (blockIdx.x * 8 + wid) * 16;
    int r0 = m0 + qr, r1 = r0 + 8;
    bool v0 = r0 < M, v1 = r1 < M;
    const float* a0 = A + (size_t)(v0 ? r0 : 0) * K;
    const float* a1 = A + (size_t)(v1 ? r1 : 0) * K;

    float acc[NB][4];
    #pragma unroll
    for (int nb = 0; nb < NB; nb++) {
        acc[nb][0] = acc[nb][1] = acc[nb][2] = acc[nb][3] = 0.f;
    }

    #pragma unroll 2
    for (int j = 0; j < KCH; j++) {
        uint32_t Ah[4];
        float2 x0 = *(const float2*)(a0 + 16 * j + qc);
        float2 x1 = *(const float2*)(a1 + 16 * j + qc);
        float2 x2 = *(const float2*)(a0 + 16 * j + qc + 8);
        float2 x3 = *(const float2*)(a1 + 16 * j + qc + 8);
        Ah[0] = packh(x0.x, x0.y);
        Ah[1] = packh(x1.x, x1.y);
        Ah[2] = packh(x2.x, x2.y);
        Ah[3] = packh(x3.x, x3.y);
        #pragma unroll
        for (int nb = 0; nb < NB; nb++) {
            const __half* ph = Whs + (8 * nb + qr) * KP + 16 * j + qc;
            const __half* pl = Wls + (8 * nb + qr) * KP + 16 * j + qc;
            uint32_t bh0 = *(const uint32_t*)ph;
            uint32_t bh1 = *(const uint32_t*)(ph + 8);
            uint32_t bl0 = *(const uint32_t*)pl;
            uint32_t bl1 = *(const uint32_t*)(pl + 8);
            mma_f16(acc[nb], Ah, bh0, bh1);
            mma_f16(acc[nb], Ah, bl0, bl1);
        }
    }

    #pragma unroll
    for (int nb = 0; nb < NB; nb++) {
        int col = 8 * nb + qc;
        float b0v = bs[col], b1v = bs[col + 1];
        float u0 = acc[nb][0] + b0v, u1 = acc[nb][1] + b1v;
        float u2 = acc[nb][2] + b0v, u3 = acc[nb][3] + b1v;
        if (RELU) {
            u0 = fmaxf(u0, 0.f); u1 = fmaxf(u1, 0.f);
            u2 = fmaxf(u2, 0.f); u3 = fmaxf(u3, 0.f);
        }
        if (v0) *(float2*)(C + (size_t)r0 * Nfull + n0 + col) = make_float2(u0, u1);
        if (v1) *(float2*)(C + (size_t)r1 * Nfull + n0 + col) = make_float2(u2, u3);
    }
}

// ================= mma.sync fused edge kernel (fp16 2-term, sorted, deduped) =================
#define EDGE3_SMEM (176128 + 1024)
#define EDGE_THREADS 256
#define EDGE_WARPS 8

template<int NC>
__device__ __forceinline__ void stage_mma(
    float acc[16][4], const uint32_t Ah[8][4],
    const __half* __restrict__ Wh, const __half* __restrict__ Wl,
    int KP, int qr, int qc)
{
    #pragma unroll
    for (int j = 0; j < NC; j++) {
        #pragma unroll
        for (int nb = 0; nb < 16; nb++) {
            const __half* ph = Wh + (8 * nb + qr) * KP + 16 * j + qc;
            const __half* pl = Wl + (8 * nb + qr) * KP + 16 * j + qc;
            uint32_t bh0 = *(const uint32_t*)ph;
            uint32_t bh1 = *(const uint32_t*)(ph + 8);
            uint32_t bl0 = *(const uint32_t*)pl;
            uint32_t bl1 = *(const uint32_t*)(pl + 8);
            mma_f16(acc[nb], Ah[j], bh0, bh1);
            mma_f16(acc[nb], Ah[j], bl0, bl1);
        }
    }
}

__global__ __launch_bounds__(EDGE_THREADS) void edge_kernel6(
    const float* __restrict__ ea,
    const int* __restrict__ src, const int* __restrict__ dst,
    const int* __restrict__ perm,
    const uint4* __restrict__ wpack,
    const float* __restrict__ be1,
    const float* __restrict__ ab, float* __restrict__ agg, int E)
{
    extern __shared__ char smem[];
    __half* W = (__half*)smem;
    float* be1s = (float*)(smem + 176128);

    int tid = threadIdx.x;
    {
        uint4* s4 = (uint4*)smem;
        for (int i = tid; i < 11008; i += EDGE_THREADS) s4[i] = wpack[i];
        if (tid < 128) be1s[tid] = be1[tid];
    }
    __syncthreads();

    const __half* We1h = W + WO_WE1H;
    const __half* We1l = W + WO_WE1L;
    const __half* Wch  = W + WO_WCH;
    const __half* Wcl  = W + WO_WCL;
    const __half* Wm2h = W + WO_WM2H;
    const __half* Wm2l = W + WO_WM2L;

    int lane = tid & 31, wid = tid >> 5;
    int qr = lane >> 2;
    int qc = (lane & 3) * 2;

    int nG = (E + 15) >> 4;
    for (int g = blockIdx.x * EDGE_WARPS + wid; g < nG; g += gridDim.x * EDGE_WARPS) {
        int p0 = g << 4;
        int pr0 = p0 + qr, pr1 = pr0 + 8;
        bool v0 = pr0 < E, v1 = pr1 < E;
        int ec0 = v0 ? perm[pr0] : 0, ec1 = v1 ? perm[pr1] : 0;
        int d0 = dst[ec0], d1 = dst[ec1];
        int s0 = src[ec0], s1 = src[ec1];

        uint32_t Ah[8][4];
        float acc[16][4];

        #pragma unroll
        for (int j = 0; j < 4; j++) {
            const float* r0p = ea + (size_t)ec0 * 64 + 16 * j + qc;
            const float* r1p = ea + (size_t)ec1 * 64 + 16 * j + qc;
            float2 x0 = *(const float2*)r0p;
            float2 x1 = *(const float2*)r1p;
            float2 x2 = *(const float2*)(r0p + 8);
            float2 x3 = *(const float2*)(r1p + 8);
            Ah[j][0] = packh(x0.x, x0.y);
            Ah[j][1] = packh(x1.x, x1.y);
            Ah[j][2] = packh(x2.x, x2.y);
            Ah[j][3] = packh(x3.x, x3.y);
        }

        // S1
        #pragma unroll
        for (int nb = 0; nb < 16; nb++)
            #pragma unroll
            for (int q = 0; q < 4; q++) acc[nb][q] = 0.f;
        stage_mma<4>(acc, Ah, We1h, We1l, 72, qr, qc);
        #pragma unroll
        for (int nb = 0; nb < 16; nb++) {
            int col = 8 * nb + qc;
            float b0 = be1s[col], b1 = be1s[col + 1];
            float u0 = fmaxf(acc[nb][0] + b0, 0.f);
            float u1 = fmaxf(acc[nb][1] + b1, 0.f);
            float u2 = fmaxf(acc[nb][2] + b0, 0.f);
            float u3 = fmaxf(acc[nb][3] + b1, 0.f);
            int j = nb >> 1, q = (nb & 1) * 2;
            Ah[j][q]     = packh(u0, u1);
            Ah[j][q + 1] = packh(u2, u3);
        }

        // S2  (bc folded into ab via bch bias in the WAB gemm)
        #pragma unroll
        for (int nb = 0; nb < 16; nb++)
            #pragma unroll
            for (int q = 0; q < 4; q++) acc[nb][q] = 0.f;
        stage_mma<8>(acc, Ah, Wch, Wcl, 136, qr, qc);
        {
            const float* a0p = ab + (size_t)d0 * 256;
            const float* a1p = ab + (size_t)d1 * 256;
            const float* b0p = ab + (size_t)s0 * 256 + 128;
            const float* b1p = ab + (size_t)s1 * 256 + 128;
            #pragma unroll
            for (int nb = 0; nb < 16; nb++) {
                int col = 8 * nb + qc;
                float2 ga0 = *(const float2*)(a0p + col);
                float2 ga1 = *(const float2*)(a1p + col);
                float2 gb0 = *(const float2*)(b0p + col);
                float2 gb1 = *(const float2*)(b1p + col);
                float u0 = fmaxf(acc[nb][0] + ga0.x + gb0.x, 0.f);
                float u1 = fmaxf(acc[nb][1] + ga0.y + gb0.y, 0.f);
                float u2 = fmaxf(acc[nb][2] + ga1.x + gb1.x, 0.f);
                float u3 = fmaxf(acc[nb][3] + ga1.y + gb1.y, 0.f);
                int j = nb >> 1, q = (nb & 1) * 2;
                Ah[j][q]     = packh(u0, u1);
                Ah[j][q + 1] = packh(u2, u3);
            }
        }

        // S3 + deduped atomic scatter (sorted dst => rows qr and qr+8 often share dst)
        #pragma unroll
        for (int nb = 0; nb < 16; nb++)
            #pragma unroll
            for (int q = 0; q < 4; q++) acc[nb][q] = 0.f;
        stage_mma<8>(acc, Ah, Wm2h, Wm2l, 136, qr, qc);
        {
            float* g0 = agg + (size_t)d0 * 128;
            float* g1 = agg + (size_t)d1 * 128;
            bool same = v1 && (d0 == d1);
            #pragma unroll
            for (int nb = 0; nb < 16; nb++) {
                int col = 8 * nb + qc;
                if (same) {
                    asm volatile("red.global.add.v2.f32 [%0], {%1, %2};"
                                 :: "l"(g0 + col),
                                    "f"(acc[nb][0] + acc[nb][2]),
                                    "f"(acc[nb][1] + acc[nb][3]) : "memory");
                } else {
                    if (v0)
                        asm volatile("red.global.add.v2.f32 [%0], {%1, %2};"
                                     :: "l"(g0 + col), "f"(acc[nb][0]), "f"(acc[nb][1]) : "memory");
                    if (v1)
                        asm volatile("red.global.add.v2.f32 [%0], {%1, %2};"
                                     :: "l"(g1 + col), "f"(acc[nb][2]), "f"(acc[nb][3]) : "memory");
                }
            }
        }
    }
}

// ================= LayerNorm + relu (+ agg re-zero for next layer) =================
__global__ void ln_kernel(float* __restrict__ agg, const int* __restrict__ rowptr,
                          const float* __restrict__ bm2, const float* __restrict__ lnw,
                          const float* __restrict__ lnb, float* __restrict__ xout, int N)
{
    int node = (blockIdx.x * blockDim.x + threadIdx.x) >> 5;
    int lane = threadIdx.x & 31;
    if (node >= N) return;
    float d = (float)(rowptr[node + 1] - rowptr[node]);
    float inv = 1.f / fmaxf(d, 1.f);
    float add = (d > 0.f) ? 1.f : 0.f;
    float4 v = ((const float4*)agg)[(size_t)node * 32 + lane];
    ((float4*)agg)[(size_t)node * 32 + lane] = make_float4(0.f, 0.f, 0.f, 0.f);
    float4 b = ((const float4*)bm2)[lane];
    v.x = v.x * inv + add * b.x;
    v.y = v.y * inv + add * b.y;
    v.z = v.z * inv + add * b.z;
    v.w = v.w * inv + add * b.w;
    float s = v.x + v.y + v.z + v.w;
    #pragma unroll
    for (int o = 16; o; o >>= 1) s += __shfl_xor_sync(0xffffffffu, s, o);
    float mu = s * (1.f / 128.f);
    float d0 = v.x - mu, d1 = v.y - mu, d2 = v.z - mu, d3 = v.w - mu;
    float q = d0 * d0 + d1 * d1 + d2 * d2 + d3 * d3;
    #pragma unroll
    for (int o = 16; o; o >>= 1) q += __shfl_xor_sync(0xffffffffu, q, o);
    float rs = rsqrtf(q * (1.f / 128.f) + 1e-5f);
    float4 w = ((const float4*)lnw)[lane];
    float4 bb = ((const float4*)lnb)[lane];
    float4 o;
    o.x = fmaxf(d0 * rs * w.x + bb.x, 0.f);
    o.y = fmaxf(d1 * rs * w.y + bb.y, 0.f);
    o.z = fmaxf(d2 * rs * w.z + bb.z, 0.f);
    o.w = fmaxf(d3 * rs * w.w + bb.w, 0.f);
    ((float4*)xout)[(size_t)node * 32 + lane] = o;
}

// ================= host =================
extern "C" void kernel_launch(void* const* d_in, const int* in_sizes, int n_in,
                              void* d_out, int out_size)
{
    const float* x    = (const float*)d_in[0];
    const float* ea   = (const float*)d_in[1];
    const int*   eidx = (const int*)  d_in[2];
    const float* Wn1  = (const float*)d_in[3];
    const float* bn1  = (const float*)d_in[4];
    const float* Wn2  = (const float*)d_in[5];
    const float* bn2  = (const float*)d_in[6];
    const float* We1  = (const float*)d_in[7];
    const float* be1  = (const float*)d_in[8];
    const float* We2  = (const float*)d_in[9];
    const float* be2  = (const float*)d_in[10];
    const float* Wm1  = (const float*)d_in[11];
    const float* bm1  = (const float*)d_in[12];
    const float* Wm2  = (const float*)d_in[13];
    const float* bm2  = (const float*)d_in[14];
    const float* lnw  = (const float*)d_in[15];
    const float* lnb  = (const float*)d_in[16];
    const float* Wf   = (const float*)d_in[17];
    const float* bf   = (const float*)d_in[18];

    int N = in_sizes[0] / 128;
    int E = in_sizes[1] / 64;
    const int* srcp = eidx;
    const int* dstp = eidx + E;

    float *h1n, *ab, *xb, *agg, *Wab, *Wc, *bch;
    int *hist, *cursor, *rowptr, *bsum, *perm;
    uint4 *wpack, *wnode, *wf;
    cudaGetSymbolAddress((void**)&h1n, g_h1n);
    cudaGetSymbolAddress((void**)&ab,  g_ab);
    cudaGetSymbolAddress((void**)&xb,  g_x);
    cudaGetSymbolAddress((void**)&agg, g_agg);
    cudaGetSymbolAddress((void**)&Wab, g_Wab);
    cudaGetSymbolAddress((void**)&Wc,  g_Wc);
    cudaGetSymbolAddress((void**)&bch, g_bch);
    cudaGetSymbolAddress((void**)&hist, g_hist);
    cudaGetSymbolAddress((void**)&cursor, g_cursor);
    cudaGetSymbolAddress((void**)&rowptr, g_rowptr);
    cudaGetSymbolAddress((void**)&bsum, g_bsum);
    cudaGetSymbolAddress((void**)&perm, g_perm);
    cudaGetSymbolAddress((void**)&wpack, g_wpack);
    cudaGetSymbolAddress((void**)&wnode, g_wnode);
    cudaGetSymbolAddress((void**)&wf, g_wf);
    __half* wb = (__half*)wpack;
    __half* nbw = (__half*)wnode;
    __half* wfb = (__half*)wf;

    cudaFuncSetAttribute(edge_kernel6, cudaFuncAttributeMaxDynamicSharedMemorySize,
                         EDGE3_SMEM);
    int smW1  = 2 * 128 * 136 * 2 + 512;   // ngemm<8,16>
    int smWab = 2 * 128 * 264 * 2 + 512;   // ngemm<16,16>
    int smWf  = 2 * 64 * 136 * 2 + 256;    // ngemm<8,8>
    cudaFuncSetAttribute(ngemm<8, 16, true>,   cudaFuncAttributeMaxDynamicSharedMemorySize, smW1);
    cudaFuncSetAttribute(ngemm<16, 16, false>, cudaFuncAttributeMaxDynamicSharedMemorySize, smWab);
    cudaFuncSetAttribute(ngemm<8, 8, false>,   cudaFuncAttributeMaxDynamicSharedMemorySize, smWf);

    int nBlk = (N + 255) / 256;   // 196 for N=50000 (<=256 required by scan2)
    zero_init<<<(N * 32 + 255) / 256, 256>>>(hist, cursor, agg, N);
    hist_kernel<<<(E + 255) / 256, 256>>>(dstp, hist, E);
    scan1<<<nBlk, 256>>>(hist, rowptr, bsum, N);
    scan2<<<1, 256>>>(bsum, nBlk);
    scan3<<<(N + 256) / 256, 256>>>(rowptr, hist, bsum, N, E);
    scatter_kernel<<<(E + 255) / 256, 256>>>(dstp, rowptr, cursor, perm, E);
    fuse_all<<<1008, 256>>>(Wn2, Wm1, We2, bn2, be2, bm1, Wab, Wc, bch);
    prep_all<<<1664, 256>>>(We1, Wc, Wm2, Wn1, Wab, Wf, wb, nbw, wfb);

    const float* curx = x;
    int gRows = (N + 127) / 128;
    for (int l = 0; l < LLAYERS; l++) {
        __half* npb = nbw + (size_t)l * NP_LAYER_ELEMS;
        ngemm<8, 16, true><<<dim3(gRows, 2), 256, smW1>>>(
            curx, (const uint4*)(npb + NP_W1), bn1 + l * 256, h1n, N, 256);
        ngemm<16, 16, false><<<dim3(gRows, 2), 256, smWab>>>(
            h1n, (const uint4*)(npb + NP_WAB), bch + l * 256, ab, N, 256);
        edge_kernel6<<<148, EDGE_THREADS, EDGE3_SMEM>>>(
            ea, srcp, dstp, perm,
            (const uint4*)(wb + (size_t)l * WP_LAYER_ELEMS),
            be1 + l * 128, ab, agg, E);
        ln_kernel<<<(N + 7) / 8, 256>>>(agg, rowptr, bm2 + l * 128, lnw + l * 128,
                                        lnb + l * 128, xb, N);
        curx = xb;
    }
    ngemm<8, 8, false><<<dim3(gRows, 1), 256, smWf>>>(
        curx, (const uint4*)wfb, bf, (float*)d_out, N, 64);
}

// round 12
// speedup vs baseline: 1.4413x; 1.1804x over previous
#include <cuda_runtime.h>
#include <cuda_bf16.h>
#include <cuda_fp16.h>
#include <cstdint>

#define MAXN 50000
#define MAXE 800000
#define LLAYERS 3

// ================= helpers =================
// pack two floats to half2: hi_v -> upper 16, lo_v -> lower 16
__device__ __forceinline__ uint32_t packh(float lo_v, float hi_v) {
    uint32_t r;
    asm("cvt.rn.f16x2.f32 %0, %1, %2;" : "=r"(r) : "f"(hi_v), "f"(lo_v));
    return r;
}

__device__ __forceinline__ void mma_f16(float* c, const uint32_t* a, uint32_t b0, uint32_t b1) {
    asm volatile(
        "mma.sync.aligned.m16n8k16.row.col.f32.f16.f16.f32 "
        "{%0,%1,%2,%3}, {%4,%5,%6,%7}, {%8,%9}, {%0,%1,%2,%3};\n"
        : "+f"(c[0]), "+f"(c[1]), "+f"(c[2]), "+f"(c[3])
        : "r"(a[0]), "r"(a[1]), "r"(a[2]), "r"(a[3]), "r"(b0), "r"(b1));
}

// ================= scratch (static device globals) =================
__device__ float g_h1n[MAXN * 256];
__device__ float g_ab [MAXN * 256];
__device__ float g_x  [MAXN * 128];
__device__ float g_agg[MAXN * 128];
__device__ float g_Wab [LLAYERS * 256 * 256];
__device__ float g_Wc  [LLAYERS * 128 * 128];
__device__ float g_bch [LLAYERS * 256];   // [bc/2 | bc/2]
// sorted-edge machinery (small)
__device__ int g_hist[MAXN];
__device__ int g_cursor[MAXN];
__device__ int g_rowptr[MAXN + 1];
__device__ int g_bsum[256];
__device__ int g_perm[MAXE];
// per-layer packed fp16 transposed edge weights, 88064 elems / layer
#define WP_LAYER_ELEMS 88064
__device__ uint4 g_wpack[LLAYERS * WP_LAYER_ELEMS * 2 / 16];
// per-layer node weights: [W1hi 256x136][W1lo][WABhi 256x264][WABlo]
#define NP_LAYER_ELEMS 204800
#define NP_W1  0
#define NP_WAB 69632
__device__ uint4 g_wnode[LLAYERS * NP_LAYER_ELEMS * 2 / 16];
__device__ uint4 g_wf[2 * 64 * 136 * 2 / 16];

#define WO_WE1H 0
#define WO_WE1L 9216
#define WO_WCH  18432
#define WO_WCL  35840
#define WO_WM2H 53248
#define WO_WM2L 70656

// ================= fused weight-fuse kernel =================
// blocks [0,768): Wab ; [768,960): Wc ; [960,1008): bch
__global__ __launch_bounds__(256) void fuse_all(
    const float* __restrict__ Wn2, const float* __restrict__ Wm1,
    const float* __restrict__ We2, const float* __restrict__ bn2,
    const float* __restrict__ be2, const float* __restrict__ bm1,
    float* __restrict__ Wab, float* __restrict__ Wc, float* __restrict__ bch)
{
    int b = blockIdx.x, tid = threadIdx.x;
    if (b < 768) {
        int l = b >> 8;
        int idx = (b & 255) * 256 + tid;
        const float* wn2 = Wn2 + (size_t)l * 256 * 128;
        const float* wm1 = Wm1 + (size_t)l * 320 * 128;
        int k = idx >> 8, j = idx & 255;
        const float* wm = (j < 128) ? (wm1 + j) : (wm1 + 128 * 128 + (j - 128));
        float acc = 0.f;
        #pragma unroll 4
        for (int t = 0; t < 128; t++) acc += wn2[k * 128 + t] * wm[t * 128];
        Wab[(size_t)l * 65536 + idx] = acc;
    } else if (b < 960) {
        int lb = b - 768;
        int l = lb / 64;
        int idx = (lb % 64) * 256 + tid;
        const float* we2 = We2 + (size_t)l * 128 * 64;
        const float* wm1 = Wm1 + (size_t)l * 320 * 128;
        int k = idx >> 7, j = idx & 127;
        float acc = 0.f;
        #pragma unroll 4
        for (int t = 0; t < 64; t++) acc += we2[k * 64 + t] * wm1[(256 + t) * 128 + j];
        Wc[(size_t)l * 16384 + idx] = acc;
    } else {
        int lb = b - 960;
        int l = lb / 16;
        int lane = tid & 31;
        int j = (lb % 16) * 8 + (tid >> 5);
        const float* wm1 = Wm1 + (size_t)l * 320 * 128;
        const float* bn2l = bn2 + l * 128;
        const float* be2l = be2 + l * 64;
        float acc = 0.f;
        #pragma unroll
        for (int k = lane; k < 128; k += 32)
            acc += bn2l[k] * (wm1[k * 128 + j] + wm1[(128 + k) * 128 + j]);
        #pragma unroll
        for (int t = lane; t < 64; t += 32)
            acc += be2l[t] * wm1[(256 + t) * 128 + j];
        #pragma unroll
        for (int o = 16; o; o >>= 1) acc += __shfl_xor_sync(0xffffffffu, acc, o);
        if (lane == 0) {
            float half = 0.5f * (bm1[l * 128 + j] + acc);
            bch[l * 256 + j] = half;
            bch[l * 256 + 128 + j] = half;
        }
    }
}

// ================= fused fp16 hi/lo transpose prep kernel =================
__device__ __forceinline__ void splitw(float w, __half* hi, __half* lo, int o) {
    __half h = __float2half_rn(w);
    hi[o] = h;
    lo[o] = __float2half_rn(w - __half2float(h));
}

// blocks: [0,96) we1t | [96,288) WcT | [288,480) Wm2T | [480,864) W1 | [864,1632) WAB | [1632,1664) Wf
__global__ __launch_bounds__(256) void prep_all(
    const float* __restrict__ We1, const float* __restrict__ WcG,
    const float* __restrict__ Wm2, const float* __restrict__ Wn1,
    const float* __restrict__ WabG, const float* __restrict__ Wf,
    __half* __restrict__ wb, __half* __restrict__ nbw,
    __half* __restrict__ wfb)
{
    int b = blockIdx.x, tid = threadIdx.x;
    if (b < 96) {
        int l = b / 32;
        int idx = (b % 32) * 256 + tid;             // 8192 ; K=64, KP=72
        int n = idx >> 6, k = idx & 63;
        float w = We1[(size_t)l * 8192 + k * 128 + n];
        __half* base = wb + (size_t)l * WP_LAYER_ELEMS;
        splitw(w, base + WO_WE1H, base + WO_WE1L, n * 72 + k);
    } else if (b < 288) {
        int lb = b - 96;
        int l = lb / 64;
        int idx = (lb % 64) * 256 + tid;            // 16384 ; K=128, KP=136
        int n = idx >> 7, k = idx & 127;
        float w = WcG[(size_t)l * 16384 + k * 128 + n];
        __half* base = wb + (size_t)l * WP_LAYER_ELEMS;
        splitw(w, base + WO_WCH, base + WO_WCL, n * 136 + k);
    } else if (b < 480) {
        int lb = b - 288;
        int l = lb / 64;
        int idx = (lb % 64) * 256 + tid;            // 16384 ; K=128, KP=136
        int n = idx >> 7, k = idx & 127;
        float w = Wm2[(size_t)l * 16384 + k * 128 + n];
        __half* base = wb + (size_t)l * WP_LAYER_ELEMS;
        splitw(w, base + WO_WM2H, base + WO_WM2L, n * 136 + k);
    } else if (b < 864) {
        int lb = b - 480;
        int l = lb / 128;
        int idx = (lb % 128) * 256 + tid;           // 32768 ; K=128,Nf=256,KP=136
        int n = idx & 255, k = idx >> 8;
        float w = Wn1[(size_t)l * 32768 + idx];
        __half* base = nbw + (size_t)l * NP_LAYER_ELEMS + NP_W1;
        splitw(w, base, base + 256 * 136, n * 136 + k);
    } else if (b < 1632) {
        int lb = b - 864;
        int l = lb / 256;
        int idx = (lb % 256) * 256 + tid;           // 65536 ; K=256,Nf=256,KP=264
        int n = idx & 255, k = idx >> 8;
        float w = WabG[(size_t)l * 65536 + idx];
        __half* base = nbw + (size_t)l * NP_LAYER_ELEMS + NP_WAB;
        splitw(w, base, base + 256 * 264, n * 264 + k);
    } else {
        int idx = (b - 1632) * 256 + tid;           // 8192 ; K=128,Nf=64,KP=136
        int n = idx & 63, k = idx >> 6;
        splitw(Wf[idx], wfb, wfb + 64 * 136, n * 136 + k);
    }
}

// ================= counting sort of edges by dst =================
__global__ void zero_init(int* __restrict__ hist, int* __restrict__ cursor,
                          float* __restrict__ agg, int N) {
    int i = blockIdx.x * blockDim.x + threadIdx.x;
    if (i < N) { hist[i] = 0; cursor[i] = 0; }
    if (i < N * 32) ((float4*)agg)[i] = make_float4(0.f, 0.f, 0.f, 0.f);
}

__global__ void hist_kernel(const int* __restrict__ dst, int* __restrict__ hist, int E) {
    int e = blockIdx.x * blockDim.x + threadIdx.x;
    if (e < E) atomicAdd(&hist[dst[e]], 1);
}

// per-block inclusive scan of 256 elems -> rowptr (inclusive), bsum[b] = block total
__global__ void scan1(const int* __restrict__ hist, int* __restrict__ rowptr,
                      int* __restrict__ bsum, int N) {
    __shared__ int s[256];
    int t = threadIdx.x, i = blockIdx.x * 256 + t;
    int v = (i < N) ? hist[i] : 0;
    s[t] = v;
    __syncthreads();
    #pragma unroll
    for (int o = 1; o < 256; o <<= 1) {
        int u = (t >= o) ? s[t - o] : 0;
        __syncthreads();
        s[t] += u;
        __syncthreads();
    }
    if (i < N) rowptr[i] = s[t];
    if (t == 255) bsum[blockIdx.x] = s[255];
}

// exclusive scan of block sums (nb <= 256), in place
__global__ void scan2(int* __restrict__ bsum, int nb) {
    __shared__ int s[256];
    int t = threadIdx.x;
    int orig = (t < nb) ? bsum[t] : 0;
    s[t] = orig;
    __syncthreads();
    #pragma unroll
    for (int o = 1; o < 256; o <<= 1) {
        int u = (t >= o) ? s[t - o] : 0;
        __syncthreads();
        s[t] += u;
        __syncthreads();
    }
    if (t < nb) bsum[t] = s[t] - orig;
}

// finalize exclusive rowptr
__global__ void scan3(int* __restrict__ rowptr, const int* __restrict__ hist,
                      const int* __restrict__ bsum, int N, int E) {
    int i = blockIdx.x * blockDim.x + threadIdx.x;
    if (i < N) rowptr[i] = rowptr[i] - hist[i] + bsum[i >> 8];
    if (i == N) rowptr[N] = E;
}

__global__ void scatter_kernel(const int* __restrict__ dst, const int* __restrict__ rowptr,
                               int* __restrict__ cursor, int* __restrict__ perm, int E) {
    int e = blockIdx.x * blockDim.x + threadIdx.x;
    if (e < E) {
        int d = dst[e];
        int pos = rowptr[d] + atomicAdd(&cursor[d], 1);
        perm[pos] = e;
    }
}

// ================= tensor-core node GEMM (fp16 2-term) =================
template<int KCH, int NB, bool RELU>
__global__ __launch_bounds__(256) void ngemm(
    const float* __restrict__ A, const uint4* __restrict__ Wt,
    const float* __restrict__ bias, float* __restrict__ C, int M, int Nfull)
{
    constexpr int K = KCH * 16;
    constexpr int KP = K + 8;
    constexpr int NT = NB * 8;
    extern __shared__ char nsm[];
    __half* Whs = (__half*)nsm;
    __half* Wls = Whs + NT * KP;
    float* bs = (float*)(Wls + NT * KP);

    int tid = threadIdx.x;
    int n0 = blockIdx.y * NT;
    {
        const uint4* hsrc = Wt + n0 * KP / 8;
        const uint4* lsrc = Wt + (Nfull * KP) / 8 + n0 * KP / 8;
        uint4* hdst = (uint4*)Whs;
        uint4* ldst = (uint4*)Wls;
        constexpr int CNT = NT * KP / 8;
        for (int i = tid; i < CNT; i += 256) { hdst[i] = hsrc[i]; ldst[i] = lsrc[i]; }
        if (tid < NT) bs[tid] = bias ? bias[n0 + tid] : 0.f;
    }
    __syncthreads();

    int lane = tid & 31, wid = tid >> 5;
    int qr = lane >> 2, qc = (lane & 3) * 2;
    int m0 = (blockIdx.x * 8 + wid) * 16;
    int r0 = m0 + qr, r1 = r0 + 8;
    bool v0 = r0 < M, v1 = r1 < M;
    const float* a0 = A + (size_t)(v0 ? r0 : 0) * K;
    const float* a1 = A + (size_t)(v1 ? r1 : 0) * K;

    float acc[NB][4];
    #pragma unroll
    for (int nb = 0; nb < NB; nb++) {
        acc[nb][0] = acc[nb][1] = acc[nb][2] = acc[nb][3] = 0.f;
    }

    #pragma unroll 2
    for (int j = 0; j < KCH; j++) {
        uint32_t Ah[4];
        float2 x0 = *(const float2*)(a0 + 16 * j + qc);
        float2 x1 = *(const float2*)(a1 + 16 * j + qc);
        float2 x2 = *(const float2*)(a0 + 16 * j + qc + 8);
        float2 x3 = *(const float2*)(a1 + 16 * j + qc + 8);
        Ah[0] = packh(x0.x, x0.y);
        Ah[1] = packh(x1.x, x1.y);
        Ah[2] = packh(x2.x, x2.y);
        Ah[3] = packh(x3.x, x3.y);
        #pragma unroll
        for (int nb = 0; nb < NB; nb++) {
            const __half* ph = Whs + (8 * nb + qr) * KP + 16 * j + qc;
            const __half* pl = Wls + (8 * nb + qr) * KP + 16 * j + qc;
            uint32_t bh0 = *(const uint32_t*)ph;
            uint32_t bh1 = *(const uint32_t*)(ph + 8);
            uint32_t bl0 = *(const uint32_t*)pl;
            uint32_t bl1 = *(const uint32_t*)(pl + 8);
            mma_f16(acc[nb], Ah, bh0, bh1);
            mma_f16(acc[nb], Ah, bl0, bl1);
        }
    }

    #pragma unroll
    for (int nb = 0; nb < NB; nb++) {
        int col = 8 * nb + qc;
        float b0v = bs[col], b1v = bs[col + 1];
        float u0 = acc[nb][0] + b0v, u1 = acc[nb][1] + b1v;
        float u2 = acc[nb][2] + b0v, u3 = acc[nb][3] + b1v;
        if (RELU) {
            u0 = fmaxf(u0, 0.f); u1 = fmaxf(u1, 0.f);
            u2 = fmaxf(u2, 0.f); u3 = fmaxf(u3, 0.f);
        }
        if (v0) *(float2*)(C + (size_t)r0 * Nfull + n0 + col) = make_float2(u0, u1);
        if (v1) *(float2*)(C + (size_t)r1 * Nfull + n0 + col) = make_float2(u2, u3);
    }
}

// ================= mma.sync fused edge kernel (fp16 2-term, 384 threads) =================
#define EDGE3_SMEM (176128 + 1024)
#define EDGE_THREADS 384
#define EDGE_WARPS 12

template<int NC>
__device__ __forceinline__ void stage_mma(
    float acc[16][4], const uint32_t Ah[8][4],
    const __half* __restrict__ Wh, const __half* __restrict__ Wl,
    int KP, int qr, int qc)
{
    #pragma unroll
    for (int j = 0; j < NC; j++) {
        #pragma unroll
        for (int nb = 0; nb < 16; nb++) {
            const __half* ph = Wh + (8 * nb + qr) * KP + 16 * j + qc;
            const __half* pl = Wl + (8 * nb + qr) * KP + 16 * j + qc;
            uint32_t bh0 = *(const uint32_t*)ph;
            uint32_t bh1 = *(const uint32_t*)(ph + 8);
            uint32_t bl0 = *(const uint32_t*)pl;
            uint32_t bl1 = *(const uint32_t*)(pl + 8);
            mma_f16(acc[nb], Ah[j], bh0, bh1);
            mma_f16(acc[nb], Ah[j], bl0, bl1);
        }
    }
}

__global__ __launch_bounds__(EDGE_THREADS, 1) void edge_kernel6(
    const float* __restrict__ ea,
    const int* __restrict__ src, const int* __restrict__ dst,
    const int* __restrict__ perm,
    const uint4* __restrict__ wpack,
    const float* __restrict__ be1,
    const float* __restrict__ ab, float* __restrict__ agg, int E)
{
    extern __shared__ char smem[];
    __half* W = (__half*)smem;
    float* be1s = (float*)(smem + 176128);

    int tid = threadIdx.x;
    {
        uint4* s4 = (uint4*)smem;
        for (int i = tid; i < 11008; i += EDGE_THREADS) s4[i] = wpack[i];
        if (tid < 128) be1s[tid] = be1[tid];
    }
    __syncthreads();

    const __half* We1h = W + WO_WE1H;
    const __half* We1l = W + WO_WE1L;
    const __half* Wch  = W + WO_WCH;
    const __half* Wcl  = W + WO_WCL;
    const __half* Wm2h = W + WO_WM2H;
    const __half* Wm2l = W + WO_WM2L;

    int lane = tid & 31, wid = tid >> 5;
    int qr = lane >> 2;
    int qc = (lane & 3) * 2;

    int nG = (E + 15) >> 4;
    for (int g = blockIdx.x * EDGE_WARPS + wid; g < nG; g += gridDim.x * EDGE_WARPS) {
        int p0 = g << 4;
        int pr0 = p0 + qr, pr1 = pr0 + 8;
        bool v0 = pr0 < E, v1 = pr1 < E;
        int ec0 = v0 ? perm[pr0] : 0, ec1 = v1 ? perm[pr1] : 0;
        int d0 = dst[ec0], d1 = dst[ec1];
        int s0 = src[ec0], s1 = src[ec1];

        uint32_t Ah[8][4];
        float acc[16][4];

        #pragma unroll
        for (int j = 0; j < 4; j++) {
            const float* r0p = ea + (size_t)ec0 * 64 + 16 * j + qc;
            const float* r1p = ea + (size_t)ec1 * 64 + 16 * j + qc;
            float2 x0 = *(const float2*)r0p;
            float2 x1 = *(const float2*)r1p;
            float2 x2 = *(const float2*)(r0p + 8);
            float2 x3 = *(const float2*)(r1p + 8);
            Ah[j][0] = packh(x0.x, x0.y);
            Ah[j][1] = packh(x1.x, x1.y);
            Ah[j][2] = packh(x2.x, x2.y);
            Ah[j][3] = packh(x3.x, x3.y);
        }

        // S1
        #pragma unroll
        for (int nb = 0; nb < 16; nb++)
            #pragma unroll
            for (int q = 0; q < 4; q++) acc[nb][q] = 0.f;
        stage_mma<4>(acc, Ah, We1h, We1l, 72, qr, qc);
        #pragma unroll
        for (int nb = 0; nb < 16; nb++) {
            int col = 8 * nb + qc;
            float b0 = be1s[col], b1 = be1s[col + 1];
            float u0 = fmaxf(acc[nb][0] + b0, 0.f);
            float u1 = fmaxf(acc[nb][1] + b1, 0.f);
            float u2 = fmaxf(acc[nb][2] + b0, 0.f);
            float u3 = fmaxf(acc[nb][3] + b1, 0.f);
            int j = nb >> 1, q = (nb & 1) * 2;
            Ah[j][q]     = packh(u0, u1);
            Ah[j][q + 1] = packh(u2, u3);
        }

        // S2  (bc folded into ab via bch bias in the WAB gemm)
        #pragma unroll
        for (int nb = 0; nb < 16; nb++)
            #pragma unroll
            for (int q = 0; q < 4; q++) acc[nb][q] = 0.f;
        stage_mma<8>(acc, Ah, Wch, Wcl, 136, qr, qc);
        {
            const float* a0p = ab + (size_t)d0 * 256;
            const float* a1p = ab + (size_t)d1 * 256;
            const float* b0p = ab + (size_t)s0 * 256 + 128;
            const float* b1p = ab + (size_t)s1 * 256 + 128;
            #pragma unroll
            for (int nb = 0; nb < 16; nb++) {
                int col = 8 * nb + qc;
                float2 ga0 = *(const float2*)(a0p + col);
                float2 ga1 = *(const float2*)(a1p + col);
                float2 gb0 = *(const float2*)(b0p + col);
                float2 gb1 = *(const float2*)(b1p + col);
                float u0 = fmaxf(acc[nb][0] + ga0.x + gb0.x, 0.f);
                float u1 = fmaxf(acc[nb][1] + ga0.y + gb0.y, 0.f);
                float u2 = fmaxf(acc[nb][2] + ga1.x + gb1.x, 0.f);
                float u3 = fmaxf(acc[nb][3] + ga1.y + gb1.y, 0.f);
                int j = nb >> 1, q = (nb & 1) * 2;
                Ah[j][q]     = packh(u0, u1);
                Ah[j][q + 1] = packh(u2, u3);
            }
        }

        // S3 + deduped atomic scatter (sorted dst => rows qr and qr+8 often share dst)
        #pragma unroll
        for (int nb = 0; nb < 16; nb++)
            #pragma unroll
            for (int q = 0; q < 4; q++) acc[nb][q] = 0.f;
        stage_mma<8>(acc, Ah, Wm2h, Wm2l, 136, qr, qc);
        {
            float* g0 = agg + (size_t)d0 * 128;
            float* g1 = agg + (size_t)d1 * 128;
            bool same = v1 && (d0 == d1);
            #pragma unroll
            for (int nb = 0; nb < 16; nb++) {
                int col = 8 * nb + qc;
                if (same) {
                    asm volatile("red.global.add.v2.f32 [%0], {%1, %2};"
                                 :: "l"(g0 + col),
                                    "f"(acc[nb][0] + acc[nb][2]),
                                    "f"(acc[nb][1] + acc[nb][3]) : "memory");
                } else {
                    if (v0)
                        asm volatile("red.global.add.v2.f32 [%0], {%1, %2};"
                                     :: "l"(g0 + col), "f"(acc[nb][0]), "f"(acc[nb][1]) : "memory");
                    if (v1)
                        asm volatile("red.global.add.v2.f32 [%0], {%1, %2};"
                                     :: "l"(g1 + col), "f"(acc[nb][2]), "f"(acc[nb][3]) : "memory");
                }
            }
        }
    }
}

// ================= LayerNorm + relu (+ agg re-zero for next layer) =================
__global__ void ln_kernel(float* __restrict__ agg, const int* __restrict__ rowptr,
                          const float* __restrict__ bm2, const float* __restrict__ lnw,
                          const float* __restrict__ lnb, float* __restrict__ xout, int N)
{
    int node = (blockIdx.x * blockDim.x + threadIdx.x) >> 5;
    int lane = threadIdx.x & 31;
    if (node >= N) return;
    float d = (float)(rowptr[node + 1] - rowptr[node]);
    float inv = 1.f / fmaxf(d, 1.f);
    float add = (d > 0.f) ? 1.f : 0.f;
    float4 v = ((const float4*)agg)[(size_t)node * 32 + lane];
    ((float4*)agg)[(size_t)node * 32 + lane] = make_float4(0.f, 0.f, 0.f, 0.f);
    float4 b = ((const float4*)bm2)[lane];
    v.x = v.x * inv + add * b.x;
    v.y = v.y * inv + add * b.y;
    v.z = v.z * inv + add * b.z;
    v.w = v.w * inv + add * b.w;
    float s = v.x + v.y + v.z + v.w;
    #pragma unroll
    for (int o = 16; o; o >>= 1) s += __shfl_xor_sync(0xffffffffu, s, o);
    float mu = s * (1.f / 128.f);
    float d0 = v.x - mu, d1 = v.y - mu, d2 = v.z - mu, d3 = v.w - mu;
    float q = d0 * d0 + d1 * d1 + d2 * d2 + d3 * d3;
    #pragma unroll
    for (int o = 16; o; o >>= 1) q += __shfl_xor_sync(0xffffffffu, q, o);
    float rs = rsqrtf(q * (1.f / 128.f) + 1e-5f);
    float4 w = ((const float4*)lnw)[lane];
    float4 bb = ((const float4*)lnb)[lane];
    float4 o;
    o.x = fmaxf(d0 * rs * w.x + bb.x, 0.f);
    o.y = fmaxf(d1 * rs * w.y + bb.y, 0.f);
    o.z = fmaxf(d2 * rs * w.z + bb.z, 0.f);
    o.w = fmaxf(d3 * rs * w.w + bb.w, 0.f);
    ((float4*)xout)[(size_t)node * 32 + lane] = o;
}

// ================= host =================
extern "C" void kernel_launch(void* const* d_in, const int* in_sizes, int n_in,
                              void* d_out, int out_size)
{
    const float* x    = (const float*)d_in[0];
    const float* ea   = (const float*)d_in[1];
    const int*   eidx = (const int*)  d_in[2];
    const float* Wn1  = (const float*)d_in[3];
    const float* bn1  = (const float*)d_in[4];
    const float* Wn2  = (const float*)d_in[5];
    const float* bn2  = (const float*)d_in[6];
    const float* We1  = (const float*)d_in[7];
    const float* be1  = (const float*)d_in[8];
    const float* We2  = (const float*)d_in[9];
    const float* be2  = (const float*)d_in[10];
    const float* Wm1  = (const float*)d_in[11];
    const float* bm1  = (const float*)d_in[12];
    const float* Wm2  = (const float*)d_in[13];
    const float* bm2  = (const float*)d_in[14];
    const float* lnw  = (const float*)d_in[15];
    const float* lnb  = (const float*)d_in[16];
    const float* Wf   = (const float*)d_in[17];
    const float* bf   = (const float*)d_in[18];

    int N = in_sizes[0] / 128;
    int E = in_sizes[1] / 64;
    const int* srcp = eidx;
    const int* dstp = eidx + E;

    float *h1n, *ab, *xb, *agg, *Wab, *Wc, *bch;
    int *hist, *cursor, *rowptr, *bsum, *perm;
    uint4 *wpack, *wnode, *wf;
    cudaGetSymbolAddress((void**)&h1n, g_h1n);
    cudaGetSymbolAddress((void**)&ab,  g_ab);
    cudaGetSymbolAddress((void**)&xb,  g_x);
    cudaGetSymbolAddress((void**)&agg, g_agg);
    cudaGetSymbolAddress((void**)&Wab, g_Wab);
    cudaGetSymbolAddress((void**)&Wc,  g_Wc);
    cudaGetSymbolAddress((void**)&bch, g_bch);
    cudaGetSymbolAddress((void**)&hist, g_hist);
    cudaGetSymbolAddress((void**)&cursor, g_cursor);
    cudaGetSymbolAddress((void**)&rowptr, g_rowptr);
    cudaGetSymbolAddress((void**)&bsum, g_bsum);
    cudaGetSymbolAddress((void**)&perm, g_perm);
    cudaGetSymbolAddress((void**)&wpack, g_wpack);
    cudaGetSymbolAddress((void**)&wnode, g_wnode);
    cudaGetSymbolAddress((void**)&wf, g_wf);
    __half* wb = (__half*)wpack;
    __half* nbw = (__half*)wnode;
    __half* wfb = (__half*)wf;

    cudaFuncSetAttribute(edge_kernel6, cudaFuncAttributeMaxDynamicSharedMemorySize,
                         EDGE3_SMEM);
    int smW1  = 2 * 128 * 136 * 2 + 512;   // ngemm<8,16>
    int smWab = 2 * 128 * 264 * 2 + 512;   // ngemm<16,16>
    int smWf  = 2 * 64 * 136 * 2 + 256;    // ngemm<8,8>
    cudaFuncSetAttribute(ngemm<8, 16, true>,   cudaFuncAttributeMaxDynamicSharedMemorySize, smW1);
    cudaFuncSetAttribute(ngemm<16, 16, false>, cudaFuncAttributeMaxDynamicSharedMemorySize, smWab);
    cudaFuncSetAttribute(ngemm<8, 8, false>,   cudaFuncAttributeMaxDynamicSharedMemorySize, smWf);

    int nBlk = (N + 255) / 256;   // 196 for N=50000 (<=256 required by scan2)
    zero_init<<<(N * 32 + 255) / 256, 256>>>(hist, cursor, agg, N);
    hist_kernel<<<(E + 255) / 256, 256>>>(dstp, hist, E);
    scan1<<<nBlk, 256>>>(hist, rowptr, bsum, N);
    scan2<<<1, 256>>>(bsum, nBlk);
    scan3<<<(N + 256) / 256, 256>>>(rowptr, hist, bsum, N, E);
    scatter_kernel<<<(E + 255) / 256, 256>>>(dstp, rowptr, cursor, perm, E);
    fuse_all<<<1008, 256>>>(Wn2, Wm1, We2, bn2, be2, bm1, Wab, Wc, bch);
    prep_all<<<1664, 256>>>(We1, Wc, Wm2, Wn1, Wab, Wf, wb, nbw, wfb);

    const float* curx = x;
    int gRows = (N + 127) / 128;
    for (int l = 0; l < LLAYERS; l++) {
        __half* npb = nbw + (size_t)l * NP_LAYER_ELEMS;
        ngemm<8, 16, true><<<dim3(gRows, 2), 256, smW1>>>(
            curx, (const uint4*)(npb + NP_W1), bn1 + l * 256, h1n, N, 256);
        ngemm<16, 16, false><<<dim3(gRows, 2), 256, smWab>>>(
            h1n, (const uint4*)(npb + NP_WAB), bch + l * 256, ab, N, 256);
        edge_kernel6<<<148, EDGE_THREADS, EDGE3_SMEM>>>(
            ea, srcp, dstp, perm,
            (const uint4*)(wb + (size_t)l * WP_LAYER_ELEMS),
            be1 + l * 128, ab, agg, E);
        ln_kernel<<<(N + 7) / 8, 256>>>(agg, rowptr, bm2 + l * 128, lnw + l * 128,
                                        lnb + l * 128, xb, N);
        curx = xb;
    }
    ngemm<8, 8, false><<<dim3(gRows, 1), 256, smWf>>>(
        curx, (const uint4*)wfb, bf, (float*)d_out, N, 64);
}